// round 6
// baseline (speedup 1.0000x reference)
#include <cuda_runtime.h>
#include <math.h>

// Problem constants
#define BATCH   4
#define SEQ     2048
#define DMODEL  1024
#define NHEAD   16
#define HD      64
#define ROWS    (BATCH*SEQ)      // 8192
#define TD      (3*DMODEL)       // 3072

// Scratch (allocation-free rule: __device__ globals, referenced directly by
// the kernels so kernel_launch performs NOTHING but kernel launches).
__device__ float g_qkv[(size_t)ROWS * TD];      // [8192, 3072]  q|k|v packed
__device__ float g_attn[(size_t)ROWS * DMODEL]; // [8192, 1024]  attention out (B,N,D)

// ---------------------------------------------------------------------------
// Tiled SGEMM: C[M,N] = A[M,K] @ B[N,K]^T (+bias). Row-major, K-major B.
// 128x128 tile, BK=8, 256 threads, 8x8 per thread.
// Per kk: 4 LDS.128 -> 64 FMA per thread (compute-bound, not LDS-bound).
// Requires M%128==0, N%128==0, K%8==0 (holds for all three uses).
// ---------------------------------------------------------------------------
#define BM 128
#define BN 128
#define BKG 8

__global__ __launch_bounds__(256) void sgemm_abt(
    const float* __restrict__ A, const float* __restrict__ B,
    const float* __restrict__ bias, float* __restrict__ C,
    int M, int N, int K)
{
    __shared__ float As[BKG][BM];
    __shared__ float Bs[BKG][BN];

    const int t  = threadIdx.x;
    const int m0 = blockIdx.y * BM;
    const int n0 = blockIdx.x * BN;
    const int tx = t & 15;          // 0..15 -> 8 cols each
    const int ty = t >> 4;          // 0..15 -> 8 rows each

    // global->shared load mapping: one float4 per thread per tile per matrix
    const int lr = t >> 1;          // 0..127 (tile row)
    const int lk = (t & 1) * 4;     // 0 or 4 (k offset)

    const float* Aptr = A + (size_t)(m0 + lr) * K + lk;
    const float* Bptr = B + (size_t)(n0 + lr) * K + lk;

    float acc[8][8];
    #pragma unroll
    for (int i = 0; i < 8; i++)
        #pragma unroll
        for (int j = 0; j < 8; j++) acc[i][j] = 0.f;

    for (int k0 = 0; k0 < K; k0 += BKG) {
        float4 av = *(const float4*)(Aptr + k0);
        float4 bv = *(const float4*)(Bptr + k0);
        As[lk+0][lr] = av.x; As[lk+1][lr] = av.y;
        As[lk+2][lr] = av.z; As[lk+3][lr] = av.w;
        Bs[lk+0][lr] = bv.x; Bs[lk+1][lr] = bv.y;
        Bs[lk+2][lr] = bv.z; Bs[lk+3][lr] = bv.w;
        __syncthreads();

        #pragma unroll
        for (int kk = 0; kk < BKG; kk++) {
            float a[8], b[8];
            *(float4*)&a[0] = *(const float4*)&As[kk][ty * 8];
            *(float4*)&a[4] = *(const float4*)&As[kk][ty * 8 + 4];
            *(float4*)&b[0] = *(const float4*)&Bs[kk][tx * 8];
            *(float4*)&b[4] = *(const float4*)&Bs[kk][tx * 8 + 4];
            #pragma unroll
            for (int i = 0; i < 8; i++)
                #pragma unroll
                for (int j = 0; j < 8; j++)
                    acc[i][j] += a[i] * b[j];
        }
        __syncthreads();
    }

    float bb[8];
    #pragma unroll
    for (int j = 0; j < 8; j++)
        bb[j] = bias ? bias[n0 + tx * 8 + j] : 0.f;

    #pragma unroll
    for (int i = 0; i < 8; i++) {
        const int m = m0 + ty * 8 + i;
        float4 r0, r1;
        r0.x = acc[i][0] + bb[0]; r0.y = acc[i][1] + bb[1];
        r0.z = acc[i][2] + bb[2]; r0.w = acc[i][3] + bb[3];
        r1.x = acc[i][4] + bb[4]; r1.y = acc[i][5] + bb[5];
        r1.z = acc[i][6] + bb[6]; r1.w = acc[i][7] + bb[7];
        *(float4*)&C[(size_t)m * N + n0 + tx * 8]     = r0;
        *(float4*)&C[(size_t)m * N + n0 + tx * 8 + 4] = r1;
    }
}

// ---------------------------------------------------------------------------
// Flash-style attention, fp32. One thread = one query row. 128 queries/block.
// K/V tiles of 64 staged in shared. Output written de-transposed to [B,N,D].
// grid: (SEQ/128, BATCH*NHEAD), block: 128
// ---------------------------------------------------------------------------
__global__ __launch_bounds__(128) void attn_kernel()
{
    __shared__ float4 Ks[64][16];  // [key row][d/4]
    __shared__ float4 Vs[64][16];

    const float* qkv = g_qkv;
    const int tid = threadIdx.x;
    const int b   = blockIdx.y >> 4;
    const int h   = blockIdx.y & 15;
    const int qi  = blockIdx.x * 128 + tid;   // query index in sequence

    const float scale = 0.125f;   // 64^-0.5

    // Load query (pre-scaled)
    const float4* qptr = (const float4*)&qkv[((size_t)(b * SEQ + qi)) * TD + h * HD];
    float4 q4[16];
    #pragma unroll
    for (int i = 0; i < 16; i++) {
        float4 v = qptr[i];
        v.x *= scale; v.y *= scale; v.z *= scale; v.w *= scale;
        q4[i] = v;
    }

    float4 o4[16];
    #pragma unroll
    for (int i = 0; i < 16; i++) o4[i] = make_float4(0.f, 0.f, 0.f, 0.f);
    float m = -INFINITY;
    float l = 0.f;

    for (int kt = 0; kt < SEQ / 64; kt++) {
        const int krow0 = kt * 64;
        // cooperative K/V tile load: 1024 float4 each, 128 threads -> 8 each
        #pragma unroll
        for (int i = tid; i < 1024; i += 128) {
            const int r = i >> 4;
            const int c = i & 15;
            const size_t base = ((size_t)(b * SEQ + krow0 + r)) * TD + h * HD + c * 4;
            Ks[r][c] = *(const float4*)&qkv[base + DMODEL];       // K at +D
            Vs[r][c] = *(const float4*)&qkv[base + 2 * DMODEL];   // V at +2D
        }
        __syncthreads();

        float s[64];
        #pragma unroll
        for (int j = 0; j < 64; j++) {
            float acc = 0.f;
            #pragma unroll
            for (int d = 0; d < 16; d++) {
                float4 k4 = Ks[j][d];
                acc += q4[d].x * k4.x + q4[d].y * k4.y + q4[d].z * k4.z + q4[d].w * k4.w;
            }
            s[j] = acc;
        }

        float mt = m;
        #pragma unroll
        for (int j = 0; j < 64; j++) mt = fmaxf(mt, s[j]);
        const float alpha = __expf(m - mt);
        m = mt;
        l *= alpha;
        #pragma unroll
        for (int i = 0; i < 16; i++) {
            o4[i].x *= alpha; o4[i].y *= alpha; o4[i].z *= alpha; o4[i].w *= alpha;
        }

        #pragma unroll
        for (int j = 0; j < 64; j++) {
            const float p = __expf(s[j] - m);
            l += p;
            #pragma unroll
            for (int d = 0; d < 16; d++) {
                float4 v4 = Vs[j][d];
                o4[d].x += p * v4.x; o4[d].y += p * v4.y;
                o4[d].z += p * v4.z; o4[d].w += p * v4.w;
            }
        }
        __syncthreads();
    }

    const float inv = 1.f / l;
    float4* optr = (float4*)&g_attn[((size_t)(b * SEQ + qi)) * DMODEL + h * HD];
    #pragma unroll
    for (int i = 0; i < 16; i++) {
        float4 v = o4[i];
        v.x *= inv; v.y *= inv; v.z *= inv; v.w *= inv;
        optr[i] = v;
    }
}

// Thin wrappers so scratch globals are used without host-side symbol queries.
__global__ __launch_bounds__(256) void qkv_gemm(const float* __restrict__ x,
                                                const float* __restrict__ w)
{
    // forward to generic gemm body via direct call is not possible per-grid;
    // instead this kernel is not used — see kernel_launch (sgemm_abt takes
    // raw pointers; device globals are passed by address from device side).
}

// Device-global address trampolines: tiny kernels write the addresses once?
// Not needed — instead we give sgemm_abt explicit device-global variants.
__global__ __launch_bounds__(256) void sgemm_qkv(const float* __restrict__ x)
{
    // Not used.
}

// ---------------------------------------------------------------------------
// To pass device-global scratch into the generic GEMM without host symbol
// lookups, we instantiate GEMM kernels that bind the globals internally.
// ---------------------------------------------------------------------------
__device__ __forceinline__ void sgemm_body(
    const float* __restrict__ A, const float* __restrict__ B,
    const float* __restrict__ bias, float* __restrict__ C,
    int M, int N, int K)
{
    __shared__ float As[BKG][BM];
    __shared__ float Bs[BKG][BN];

    const int t  = threadIdx.x;
    const int m0 = blockIdx.y * BM;
    const int n0 = blockIdx.x * BN;
    const int tx = t & 15;
    const int ty = t >> 4;
    const int lr = t >> 1;
    const int lk = (t & 1) * 4;

    const float* Aptr = A + (size_t)(m0 + lr) * K + lk;
    const float* Bptr = B + (size_t)(n0 + lr) * K + lk;

    float acc[8][8];
    #pragma unroll
    for (int i = 0; i < 8; i++)
        #pragma unroll
        for (int j = 0; j < 8; j++) acc[i][j] = 0.f;

    for (int k0 = 0; k0 < K; k0 += BKG) {
        float4 av = *(const float4*)(Aptr + k0);
        float4 bv = *(const float4*)(Bptr + k0);
        As[lk+0][lr] = av.x; As[lk+1][lr] = av.y;
        As[lk+2][lr] = av.z; As[lk+3][lr] = av.w;
        Bs[lk+0][lr] = bv.x; Bs[lk+1][lr] = bv.y;
        Bs[lk+2][lr] = bv.z; Bs[lk+3][lr] = bv.w;
        __syncthreads();

        #pragma unroll
        for (int kk = 0; kk < BKG; kk++) {
            float a[8], b[8];
            *(float4*)&a[0] = *(const float4*)&As[kk][ty * 8];
            *(float4*)&a[4] = *(const float4*)&As[kk][ty * 8 + 4];
            *(float4*)&b[0] = *(const float4*)&Bs[kk][tx * 8];
            *(float4*)&b[4] = *(const float4*)&Bs[kk][tx * 8 + 4];
            #pragma unroll
            for (int i = 0; i < 8; i++)
                #pragma unroll
                for (int j = 0; j < 8; j++)
                    acc[i][j] += a[i] * b[j];
        }
        __syncthreads();
    }

    float bb[8];
    #pragma unroll
    for (int j = 0; j < 8; j++)
        bb[j] = bias ? bias[n0 + tx * 8 + j] : 0.f;

    #pragma unroll
    for (int i = 0; i < 8; i++) {
        const int m = m0 + ty * 8 + i;
        float4 r0, r1;
        r0.x = acc[i][0] + bb[0]; r0.y = acc[i][1] + bb[1];
        r0.z = acc[i][2] + bb[2]; r0.w = acc[i][3] + bb[3];
        r1.x = acc[i][4] + bb[4]; r1.y = acc[i][5] + bb[5];
        r1.z = acc[i][6] + bb[6]; r1.w = acc[i][7] + bb[7];
        *(float4*)&C[(size_t)m * N + n0 + tx * 8]     = r0;
        *(float4*)&C[(size_t)m * N + n0 + tx * 8 + 4] = r1;
    }
}

// GEMM 1: qkv = x @ w_qkv^T   (C -> g_qkv)
__global__ __launch_bounds__(256) void gemm1(const float* __restrict__ x,
                                             const float* __restrict__ w)
{
    sgemm_body(x, w, nullptr, g_qkv, ROWS, TD, DMODEL);
}

// GEMM 2: out = attn @ w_out^T + b   (A <- g_attn)
__global__ __launch_bounds__(256) void gemm2(const float* __restrict__ w,
                                             const float* __restrict__ bias,
                                             float* __restrict__ out)
{
    sgemm_body(g_attn, w, bias, out, ROWS, DMODEL, DMODEL);
}

// ---------------------------------------------------------------------------
extern "C" void kernel_launch(void* const* d_in, const int* in_sizes, int n_in,
                              void* d_out, int out_size)
{
    const float* x     = (const float*)d_in[0];   // [4,2048,1024]
    const float* w_qkv = (const float*)d_in[1];   // [3072,1024]
    const float* w_out = (const float*)d_in[2];   // [1024,1024]
    const float* b_out = (const float*)d_in[3];   // [1024]
    float* out = (float*)d_out;                   // [4,2048,1024]

    // 1) QKV projection: [8192,1024] @ [3072,1024]^T -> g_qkv [8192,3072]
    gemm1<<<dim3(TD / BN, ROWS / BM), 256>>>(x, w_qkv);

    // 2) Attention (flash, online softmax) -> g_attn in [B,N,D] layout
    attn_kernel<<<dim3(SEQ / 128, BATCH * NHEAD), 128>>>();

    // 3) Output projection + bias: [8192,1024] @ [1024,1024]^T + b -> d_out
    gemm2<<<dim3(DMODEL / BN, ROWS / BM), 256>>>(w_out, b_out, out);
}

// round 7
// speedup vs baseline: 2.9415x; 2.9415x over previous
#include <cuda_runtime.h>
#include <math.h>

// Problem constants
#define BATCH   4
#define SEQ     2048
#define DMODEL  1024
#define NHEAD   16
#define HD      64
#define ROWS    (BATCH*SEQ)      // 8192
#define TD      (3*DMODEL)       // 3072

// Scratch (__device__ globals; kernel_launch does nothing but launches)
__device__ float g_qkv[(size_t)ROWS * TD];              // [8192,3072] q|k|v
__device__ float g_attn[(size_t)ROWS * DMODEL];         // [8192,1024] attn out, [B,N,D]
__device__ float g_qT[(size_t)BATCH*NHEAD*HD*SEQ];      // [bh][d][s], pre-scaled by 1/8
__device__ float g_kT[(size_t)BATCH*NHEAD*HD*SEQ];      // [bh][d][s]

// ---------------------------------------------------------------------------
// SGEMM: C[M,N] = A[M,K] @ B[N,K]^T (+bias). 128x128 tile, BK=8, 256 thr,
// 8x8 per thread split as 2x(4+4) halves at 16B stride -> conflict-free LDS.
// Register prefetch of the next k-slice hides LDG latency behind compute.
// ---------------------------------------------------------------------------
#define BM 128
#define BN 128
#define BKG 8

__device__ __forceinline__ void sgemm_body(
    const float* __restrict__ A, const float* __restrict__ B,
    const float* __restrict__ bias, float* __restrict__ C,
    int M, int N, int K)
{
    __shared__ float As[BKG][BM];
    __shared__ float Bs[BKG][BN];

    const int t  = threadIdx.x;
    const int m0 = blockIdx.y * BM;
    const int n0 = blockIdx.x * BN;
    const int tx = t & 15;          // col groups: tx*4 and 64+tx*4
    const int ty = t >> 4;          // row groups: ty*4 and 64+ty*4
    const int lr = t >> 1;          // 0..127 (tile row for loads)
    const int lk = (t & 1) * 4;     // 0 or 4

    const float* Aptr = A + (size_t)(m0 + lr) * K + lk;
    const float* Bptr = B + (size_t)(n0 + lr) * K + lk;

    float acc[8][8];
    #pragma unroll
    for (int i = 0; i < 8; i++)
        #pragma unroll
        for (int j = 0; j < 8; j++) acc[i][j] = 0.f;

    // prefetch k0 = 0
    float4 av = *(const float4*)Aptr;
    float4 bv = *(const float4*)Bptr;

    for (int k0 = 0; k0 < K; k0 += BKG) {
        As[lk+0][lr] = av.x; As[lk+1][lr] = av.y;
        As[lk+2][lr] = av.z; As[lk+3][lr] = av.w;
        Bs[lk+0][lr] = bv.x; Bs[lk+1][lr] = bv.y;
        Bs[lk+2][lr] = bv.z; Bs[lk+3][lr] = bv.w;
        __syncthreads();

        if (k0 + BKG < K) {   // prefetch next slice while computing this one
            av = *(const float4*)(Aptr + k0 + BKG);
            bv = *(const float4*)(Bptr + k0 + BKG);
        }

        #pragma unroll
        for (int kk = 0; kk < BKG; kk++) {
            float a[8], b[8];
            *(float4*)&a[0] = *(const float4*)&As[kk][ty * 4];        // broadcast
            *(float4*)&a[4] = *(const float4*)&As[kk][64 + ty * 4];   // broadcast
            *(float4*)&b[0] = *(const float4*)&Bs[kk][tx * 4];        // conflict-free
            *(float4*)&b[4] = *(const float4*)&Bs[kk][64 + tx * 4];   // conflict-free
            #pragma unroll
            for (int i = 0; i < 8; i++)
                #pragma unroll
                for (int j = 0; j < 8; j++)
                    acc[i][j] += a[i] * b[j];
        }
        __syncthreads();
    }

    float bb[8];
    #pragma unroll
    for (int ch = 0; ch < 2; ch++)
        #pragma unroll
        for (int j = 0; j < 4; j++)
            bb[ch*4+j] = bias ? bias[n0 + ch*64 + tx*4 + j] : 0.f;

    #pragma unroll
    for (int rh = 0; rh < 2; rh++) {
        #pragma unroll
        for (int i = 0; i < 4; i++) {
            const int m = m0 + rh*64 + ty*4 + i;
            #pragma unroll
            for (int ch = 0; ch < 2; ch++) {
                float4 r;
                r.x = acc[rh*4+i][ch*4+0] + bb[ch*4+0];
                r.y = acc[rh*4+i][ch*4+1] + bb[ch*4+1];
                r.z = acc[rh*4+i][ch*4+2] + bb[ch*4+2];
                r.w = acc[rh*4+i][ch*4+3] + bb[ch*4+3];
                *(float4*)&C[(size_t)m * N + n0 + ch*64 + tx*4] = r;
            }
        }
    }
}

__global__ __launch_bounds__(256) void gemm1(const float* __restrict__ x,
                                             const float* __restrict__ w)
{
    sgemm_body(x, w, nullptr, g_qkv, ROWS, TD, DMODEL);
}

__global__ __launch_bounds__(256) void gemm2(const float* __restrict__ w,
                                             const float* __restrict__ bias,
                                             float* __restrict__ out)
{
    sgemm_body(g_attn, w, bias, out, ROWS, DMODEL, DMODEL);
}

// ---------------------------------------------------------------------------
// Transpose Q and K per head: g_qkv[b][s][part*1024 + h*64 + d]
//   -> g_qT/g_kT[(bh*64 + d)*2048 + s].  Q is pre-scaled by 1/8.
// grid (SEQ/32, 4, 64), block (32,8). 32x32 smem tiles, padded.
// ---------------------------------------------------------------------------
__global__ __launch_bounds__(256) void transpose_qk()
{
    __shared__ float tile[32][33];
    const int bh = blockIdx.z;                 // 0..63
    const int b  = bh >> 4, h = bh & 15;
    const int part = blockIdx.y >> 1;          // 0 = Q, 1 = K
    const int d0 = (blockIdx.y & 1) * 32;
    const int s0 = blockIdx.x * 32;
    const int tx = threadIdx.x, ty = threadIdx.y;
    const float scale = part ? 1.0f : 0.125f;  // fold 64^-0.5 into Q

    const size_t inbase = (size_t)b * SEQ * TD + (size_t)part * DMODEL + h * HD;
    #pragma unroll
    for (int r = 0; r < 4; r++) {
        const int s = s0 + ty + r * 8;
        tile[ty + r*8][tx] = g_qkv[inbase + (size_t)s * TD + d0 + tx];
    }
    __syncthreads();

    float* outp = part ? g_kT : g_qT;
    const size_t obase = (size_t)bh * HD * SEQ;
    #pragma unroll
    for (int r = 0; r < 4; r++) {
        const int d = d0 + ty + r * 8;
        outp[obase + (size_t)d * SEQ + s0 + tx] = tile[tx][ty + r*8] * scale;
    }
}

// ---------------------------------------------------------------------------
// Flash attention, 2D-tiled. Block = 256 thr (16x16), 64 queries x 64-key tiles.
// Thread (ty,tx): scores s[4q][4k], output o[4q][4d] (dims tx*4..+3).
// Smem: sQ = Qt[d][q], sKP = Kt[d][k] (reused as Ps[q][k]), sV = V[k][d].
// All hot LDS are broadcast or conflict-free; K/V register-prefetched.
// grid (SEQ/64, BATCH*NHEAD)
// ---------------------------------------------------------------------------
__global__ __launch_bounds__(256) void attn_kernel()
{
    __shared__ float sQ [64 * 64];   // Qt[d][q]
    __shared__ float sKP[64 * 64];   // Kt[d][k], then Ps[q][k]
    __shared__ float sV [64 * 64];   // V[k][d]

    const int t  = threadIdx.x;
    const int tx = t & 15;
    const int ty = t >> 4;
    const int bh = blockIdx.y;
    const int b  = bh >> 4, h = bh & 15;
    const int q0 = blockIdx.x * 64;

    const size_t qtb = (size_t)bh * HD * SEQ;   // base of this head in g_qT/g_kT
    const int    c4  = tx * 4;

    // Stage Q tile: Qt[d][q] from g_qT (coalesced LDG, conflict-free STS)
    #pragma unroll
    for (int n = 0; n < 4; n++) {
        const int d = ty + n * 16;
        float4 v = *(const float4*)&g_qT[qtb + (size_t)d * SEQ + q0 + c4];
        *(float4*)&sQ[d * 64 + c4] = v;
    }

    // Prefetch K/V tile 0 into registers
    float4 kreg[4], vreg[4];
    #pragma unroll
    for (int n = 0; n < 4; n++) {
        const int r = ty + n * 16;
        kreg[n] = *(const float4*)&g_kT[qtb + (size_t)r * SEQ + 0 + c4];
        vreg[n] = *(const float4*)&g_qkv[(size_t)(b * SEQ + r) * TD + 2 * DMODEL + h * HD + c4];
    }

    float4 o4[4];
    #pragma unroll
    for (int i = 0; i < 4; i++) o4[i] = make_float4(0.f, 0.f, 0.f, 0.f);
    float m[4] = {-INFINITY, -INFINITY, -INFINITY, -INFINITY};
    float l[4] = {0.f, 0.f, 0.f, 0.f};

    for (int kt = 0; kt < SEQ / 64; kt++) {
        // Commit prefetched K/V tile to smem
        #pragma unroll
        for (int n = 0; n < 4; n++) {
            const int r = ty + n * 16;
            *(float4*)&sKP[r * 64 + c4] = kreg[n];  // Kt[d][k]
            *(float4*)&sV [r * 64 + c4] = vreg[n];  // V[k][d]
        }
        __syncthreads();                             // (B) tiles visible

        if (kt + 1 < SEQ / 64) {                     // prefetch next tile
            const int k1 = (kt + 1) * 64;
            #pragma unroll
            for (int n = 0; n < 4; n++) {
                const int r = ty + n * 16;
                kreg[n] = *(const float4*)&g_kT[qtb + (size_t)r * SEQ + k1 + c4];
                vreg[n] = *(const float4*)&g_qkv[(size_t)(b * SEQ + k1 + r) * TD + 2 * DMODEL + h * HD + c4];
            }
        }

        // Scores: s[i][j] = sum_d Qt[d][ty*4+i] * Kt[d][tx*4+j]
        float s[4][4];
        #pragma unroll
        for (int i = 0; i < 4; i++)
            #pragma unroll
            for (int j = 0; j < 4; j++) s[i][j] = 0.f;

        #pragma unroll 8
        for (int d = 0; d < 64; d++) {
            float4 qa = *(const float4*)&sQ [d * 64 + ty * 4];   // broadcast
            float4 kb = *(const float4*)&sKP[d * 64 + tx * 4];   // conflict-free
            const float a[4] = {qa.x, qa.y, qa.z, qa.w};
            const float k[4] = {kb.x, kb.y, kb.z, kb.w};
            #pragma unroll
            for (int i = 0; i < 4; i++)
                #pragma unroll
                for (int j = 0; j < 4; j++)
                    s[i][j] += a[i] * k[j];
        }

        // Online softmax (row reductions across the 16-lane tx-group)
        #pragma unroll
        for (int i = 0; i < 4; i++) {
            float mx = fmaxf(fmaxf(s[i][0], s[i][1]), fmaxf(s[i][2], s[i][3]));
            #pragma unroll
            for (int d = 1; d < 16; d <<= 1)
                mx = fmaxf(mx, __shfl_xor_sync(0xffffffffu, mx, d));
            const float mn = fmaxf(m[i], mx);
            const float al = __expf(m[i] - mn);      // first tile: exp(-inf)=0
            m[i] = mn;
            float rs = 0.f;
            #pragma unroll
            for (int j = 0; j < 4; j++) {
                s[i][j] = __expf(s[i][j] - mn);
                rs += s[i][j];
            }
            #pragma unroll
            for (int d = 1; d < 16; d <<= 1)
                rs += __shfl_xor_sync(0xffffffffu, rs, d);
            l[i] = l[i] * al + rs;
            o4[i].x *= al; o4[i].y *= al; o4[i].z *= al; o4[i].w *= al;
        }

        __syncthreads();                             // (D) Kt reads finished
        // Store P: Ps[q][k] (conflict-free STS.128)
        #pragma unroll
        for (int i = 0; i < 4; i++)
            *(float4*)&sKP[(ty * 4 + i) * 64 + tx * 4] =
                make_float4(s[i][0], s[i][1], s[i][2], s[i][3]);
        __syncthreads();                             // (E) P visible

        // PV: o[q][d] += sum_j Ps[q][j] * V[j][d]
        #pragma unroll 4
        for (int j4 = 0; j4 < 16; j4++) {
            float4 vv0 = *(const float4*)&sV[(j4*4 + 0) * 64 + tx * 4];
            float4 vv1 = *(const float4*)&sV[(j4*4 + 1) * 64 + tx * 4];
            float4 vv2 = *(const float4*)&sV[(j4*4 + 2) * 64 + tx * 4];
            float4 vv3 = *(const float4*)&sV[(j4*4 + 3) * 64 + tx * 4];
            #pragma unroll
            for (int i = 0; i < 4; i++) {
                float4 p = *(const float4*)&sKP[(ty*4 + i) * 64 + j4 * 4];  // broadcast
                o4[i].x += p.x*vv0.x + p.y*vv1.x + p.z*vv2.x + p.w*vv3.x;
                o4[i].y += p.x*vv0.y + p.y*vv1.y + p.z*vv2.y + p.w*vv3.y;
                o4[i].z += p.x*vv0.z + p.y*vv1.z + p.z*vv2.z + p.w*vv3.z;
                o4[i].w += p.x*vv0.w + p.y*vv1.w + p.z*vv2.w + p.w*vv3.w;
            }
        }
        __syncthreads();                             // (C) Ps/V reads finished
    }

    // Epilogue: normalize + write de-transposed [B,N,D]
    #pragma unroll
    for (int i = 0; i < 4; i++) {
        const float inv = 1.f / l[i];
        float4 v = o4[i];
        v.x *= inv; v.y *= inv; v.z *= inv; v.w *= inv;
        *(float4*)&g_attn[(size_t)(b * SEQ + q0 + ty*4 + i) * DMODEL + h * HD + tx * 4] = v;
    }
}

// ---------------------------------------------------------------------------
extern "C" void kernel_launch(void* const* d_in, const int* in_sizes, int n_in,
                              void* d_out, int out_size)
{
    const float* x     = (const float*)d_in[0];   // [4,2048,1024]
    const float* w_qkv = (const float*)d_in[1];   // [3072,1024]
    const float* w_out = (const float*)d_in[2];   // [1024,1024]
    const float* b_out = (const float*)d_in[3];   // [1024]
    float* out = (float*)d_out;                   // [4,2048,1024]

    // 1) QKV projection -> g_qkv
    gemm1<<<dim3(TD / BN, ROWS / BM), 256>>>(x, w_qkv);

    // 2) Per-head transpose of Q (scaled) and K -> g_qT / g_kT
    transpose_qk<<<dim3(SEQ / 32, 4, BATCH * NHEAD), dim3(32, 8)>>>();

    // 3) Flash attention -> g_attn in [B,N,D]
    attn_kernel<<<dim3(SEQ / 64, BATCH * NHEAD), 256>>>();

    // 4) Output projection + bias -> d_out
    gemm2<<<dim3(DMODEL / BN, ROWS / BM), 256>>>(w_out, b_out, out);
}

// round 10
// speedup vs baseline: 3.5766x; 1.2159x over previous
#include <cuda_runtime.h>
#include <cuda_bf16.h>
#include <math.h>
#include <stdint.h>

// Problem constants
#define BATCH   4
#define SEQ     2048
#define DMODEL  1024
#define NHEAD   16
#define HD      64
#define ROWS    (BATCH*SEQ)      // 8192
#define TD      (3*DMODEL)       // 3072

// Scratch (__device__ globals; kernel_launch does nothing but launches)
__device__ float g_qkv[(size_t)ROWS * TD];              // [8192,3072] q|k|v
__device__ float g_attn[(size_t)ROWS * DMODEL];         // [8192,1024] attn out, [B,N,D]
__device__ float g_qT[(size_t)BATCH*NHEAD*HD*SEQ];      // [bh][d][s], pre-scaled by 1/8
__device__ float g_kT[(size_t)BATCH*NHEAD*HD*SEQ];      // [bh][d][s]

// ===========================================================================
// mma.sync helpers (base ISA — no sm_103a-only features)
// ===========================================================================
__device__ __forceinline__ uint32_t smem_u32(const void* p) {
    uint32_t a;
    asm("{ .reg .u64 t; cvta.to.shared.u64 t, %1; cvt.u32.u64 %0, t; }"
        : "=r"(a) : "l"(p));
    return a;
}

__device__ __forceinline__ void ldmatrix_x4(uint32_t& r0, uint32_t& r1,
                                            uint32_t& r2, uint32_t& r3,
                                            uint32_t addr) {
    asm volatile("ldmatrix.sync.aligned.m8n8.x4.shared.b16 {%0,%1,%2,%3}, [%4];"
                 : "=r"(r0), "=r"(r1), "=r"(r2), "=r"(r3) : "r"(addr));
}

__device__ __forceinline__ void ldmatrix_x2(uint32_t& r0, uint32_t& r1,
                                            uint32_t addr) {
    asm volatile("ldmatrix.sync.aligned.m8n8.x2.shared.b16 {%0,%1}, [%2];"
                 : "=r"(r0), "=r"(r1) : "r"(addr));
}

__device__ __forceinline__ void mma_bf16(float* d, const uint32_t* a,
                                         const uint32_t* b) {
    asm volatile(
        "mma.sync.aligned.m16n8k16.row.col.f32.bf16.bf16.f32 "
        "{%0,%1,%2,%3}, {%4,%5,%6,%7}, {%8,%9}, {%0,%1,%2,%3};"
        : "+f"(d[0]), "+f"(d[1]), "+f"(d[2]), "+f"(d[3])
        : "r"(a[0]), "r"(a[1]), "r"(a[2]), "r"(a[3]), "r"(b[0]), "r"(b[1]));
}

// smem tile layout: 128 rows x 32 bf16 (64 B/row), 16B chunks XOR-swizzled:
//   off(r, c) = r*64 + ((c ^ ((r>>1)&3)) << 4)      (conflict-free STS + ldmatrix)
__device__ __forceinline__ uint32_t tile_off(int r, int c) {
    return (uint32_t)(r * 64 + (((c ^ ((r >> 1) & 3)) & 3) << 4));
}

// split 16 fp32 -> 16 bf16 hi + 16 bf16 lo (two uint4 each)
__device__ __forceinline__ void split16(const float* v, uint4* hi, uint4* lo) {
    uint32_t h[8], l[8];
    #pragma unroll
    for (int p = 0; p < 8; p++) {
        float a = v[2*p], b = v[2*p+1];
        __nv_bfloat16 ha = __float2bfloat16_rn(a);
        __nv_bfloat16 hb = __float2bfloat16_rn(b);
        float ra = a - __bfloat162float(ha);
        float rb = b - __bfloat162float(hb);
        __nv_bfloat162 hh = __halves2bfloat162(ha, hb);
        __nv_bfloat162 ll = __halves2bfloat162(__float2bfloat16_rn(ra),
                                               __float2bfloat16_rn(rb));
        h[p] = *reinterpret_cast<uint32_t*>(&hh);
        l[p] = *reinterpret_cast<uint32_t*>(&ll);
    }
    hi[0] = make_uint4(h[0], h[1], h[2], h[3]);
    hi[1] = make_uint4(h[4], h[5], h[6], h[7]);
    lo[0] = make_uint4(l[0], l[1], l[2], l[3]);
    lo[1] = make_uint4(l[4], l[5], l[6], l[7]);
}

// ===========================================================================
// Tensor-core GEMM (bf16x3, mma.sync): C[M,N] = A[M,K] @ B[N,K]^T (+bias).
// 128x128 CTA tile, BK=32, 256 threads (8 warps, 2m x 4n), warp tile 64x32.
// ===========================================================================
__device__ __forceinline__ void gemm_mma_body(
    const float* __restrict__ A, const float* __restrict__ B,
    const float* __restrict__ bias, float* __restrict__ C,
    int M, int N, int K)
{
    __shared__ uint8_t sAhi[8192], sAlo[8192], sBhi[8192], sBlo[8192];

    const int t    = threadIdx.x;
    const int lane = t & 31;
    const int wid  = t >> 5;
    const int wm   = wid & 1;        // 0..1 -> 64-row half
    const int wn   = wid >> 1;       // 0..3 -> 32-col quarter
    const int m0   = blockIdx.y * 128;
    const int n0   = blockIdx.x * 128;

    const uint32_t bAhi = smem_u32(sAhi), bAlo = smem_u32(sAlo);
    const uint32_t bBhi = smem_u32(sBhi), bBlo = smem_u32(sBlo);

    // staging assignment: row r = t>>1, 16-element half h = t&1
    const int sr = t >> 1;
    const int sh = t & 1;
    const uint32_t so0 = tile_off(sr, sh * 2);
    const uint32_t so1 = tile_off(sr, sh * 2 + 1);
    const float* Ap = A + (size_t)(m0 + sr) * K + sh * 16;
    const float* Bp = B + (size_t)(n0 + sr) * K + sh * 16;

    // fragment ldmatrix addresses (depend only on lane/warp)
    const int arow = wm * 64 + (lane & 15);      // + mt*16
    const int acol_lane = lane >> 4;             // + ks*2
    const int brow = wn * 32 + (lane & 7);       // + nt*8
    const int bcol_lane = (lane >> 3) & 1;       // + ks*2

    float d[4][4][4];
    #pragma unroll
    for (int mt = 0; mt < 4; mt++)
        #pragma unroll
        for (int nt = 0; nt < 4; nt++)
            #pragma unroll
            for (int e = 0; e < 4; e++) d[mt][nt][e] = 0.f;

    // prefetch chunk 0
    float va[16], vb[16];
    #pragma unroll
    for (int q = 0; q < 4; q++) {
        *(float4*)&va[q*4] = *(const float4*)(Ap + q*4);
        *(float4*)&vb[q*4] = *(const float4*)(Bp + q*4);
    }

    const int nchunk = K >> 5;
    for (int c = 0; c < nchunk; c++) {
        // commit staged chunk (split fp32 -> bf16 hi/lo)
        uint4 hi[2], lo[2];
        split16(va, hi, lo);
        *(uint4*)(sAhi + so0) = hi[0]; *(uint4*)(sAhi + so1) = hi[1];
        *(uint4*)(sAlo + so0) = lo[0]; *(uint4*)(sAlo + so1) = lo[1];
        split16(vb, hi, lo);
        *(uint4*)(sBhi + so0) = hi[0]; *(uint4*)(sBhi + so1) = hi[1];
        *(uint4*)(sBlo + so0) = lo[0]; *(uint4*)(sBlo + so1) = lo[1];
        __syncthreads();

        if (c + 1 < nchunk) {   // prefetch next chunk
            const float* ان = Ap + (c + 1) * 32;
            const float* Bn = Bp + (c + 1) * 32;
            #pragma unroll
            for (int q = 0; q < 4; q++) {
                *(float4*)&va[q*4] = *(const float4*)(ان + q*4);
                *(float4*)&vb[q*4] = *(const float4*)(Bn + q*4);
            }
        }

        #pragma unroll
        for (int ks = 0; ks < 2; ks++) {
            uint32_t a_hi[4][4], a_lo[4][4], b_hi[4][2], b_lo[4][2];
            #pragma unroll
            for (int mt = 0; mt < 4; mt++) {
                const uint32_t off = tile_off(arow + mt * 16, ks * 2 + acol_lane);
                ldmatrix_x4(a_hi[mt][0], a_hi[mt][1], a_hi[mt][2], a_hi[mt][3], bAhi + off);
                ldmatrix_x4(a_lo[mt][0], a_lo[mt][1], a_lo[mt][2], a_lo[mt][3], bAlo + off);
            }
            #pragma unroll
            for (int nt = 0; nt < 4; nt++) {
                const uint32_t off = tile_off(brow + nt * 8, ks * 2 + bcol_lane);
                ldmatrix_x2(b_hi[nt][0], b_hi[nt][1], bBhi + off);
                ldmatrix_x2(b_lo[nt][0], b_lo[nt][1], bBlo + off);
            }
            #pragma unroll
            for (int mt = 0; mt < 4; mt++)
                #pragma unroll
                for (int nt = 0; nt < 4; nt++) {
                    mma_bf16(d[mt][nt], a_hi[mt], b_hi[nt]);
                    mma_bf16(d[mt][nt], a_hi[mt], b_lo[nt]);
                    mma_bf16(d[mt][nt], a_lo[mt], b_hi[nt]);
                }
        }
        __syncthreads();
    }

    // Epilogue: c-frag -> gmem (+bias). Thread holds rows (L>>2, L>>2+8),
    // cols (L&3)*2..+1 of each 16x8 tile.
    const int er = lane >> 2;
    const int ec = (lane & 3) * 2;
    #pragma unroll
    for (int nt = 0; nt < 4; nt++) {
        const int col = n0 + wn * 32 + nt * 8 + ec;
        float bx = 0.f, by = 0.f;
        if (bias) { bx = bias[col]; by = bias[col + 1]; }
        #pragma unroll
        for (int mt = 0; mt < 4; mt++) {
            const int row = m0 + wm * 64 + mt * 16 + er;
            float2 lo2 = make_float2(d[mt][nt][0] + bx, d[mt][nt][1] + by);
            float2 hi2 = make_float2(d[mt][nt][2] + bx, d[mt][nt][3] + by);
            *(float2*)&C[(size_t)row * N + col]       = lo2;
            *(float2*)&C[(size_t)(row + 8) * N + col] = hi2;
        }
    }
}

__global__ __launch_bounds__(256) void gemm1_tc(const float* __restrict__ x,
                                                const float* __restrict__ w)
{
    gemm_mma_body(x, w, nullptr, g_qkv, ROWS, TD, DMODEL);
}

__global__ __launch_bounds__(256) void gemm2_tc(const float* __restrict__ w,
                                                const float* __restrict__ bias,
                                                float* __restrict__ out)
{
    gemm_mma_body(g_attn, w, bias, out, ROWS, DMODEL, DMODEL);
}

// ---------------------------------------------------------------------------
// Transpose Q and K per head (unchanged from R7 — verified correct)
// ---------------------------------------------------------------------------
__global__ __launch_bounds__(256) void transpose_qk()
{
    __shared__ float tile[32][33];
    const int bh = blockIdx.z;                 // 0..63
    const int b  = bh >> 4, h = bh & 15;
    const int part = blockIdx.y >> 1;          // 0 = Q, 1 = K
    const int d0 = (blockIdx.y & 1) * 32;
    const int s0 = blockIdx.x * 32;
    const int tx = threadIdx.x, ty = threadIdx.y;
    const float scale = part ? 1.0f : 0.125f;  // fold 64^-0.5 into Q

    const size_t inbase = (size_t)b * SEQ * TD + (size_t)part * DMODEL + h * HD;
    #pragma unroll
    for (int r = 0; r < 4; r++) {
        const int s = s0 + ty + r * 8;
        tile[ty + r*8][tx] = g_qkv[inbase + (size_t)s * TD + d0 + tx];
    }
    __syncthreads();

    float* outp = part ? g_kT : g_qT;
    const size_t obase = (size_t)bh * HD * SEQ;
    #pragma unroll
    for (int r = 0; r < 4; r++) {
        const int d = d0 + ty + r * 8;
        outp[obase + (size_t)d * SEQ + s0 + tx] = tile[tx][ty + r*8] * scale;
    }
}

// ---------------------------------------------------------------------------
// Flash attention, 2D-tiled (unchanged from R7 — verified correct)
// ---------------------------------------------------------------------------
__global__ __launch_bounds__(256) void attn_kernel()
{
    __shared__ float sQ [64 * 64];   // Qt[d][q]
    __shared__ float sKP[64 * 64];   // Kt[d][k], then Ps[q][k]
    __shared__ float sV [64 * 64];   // V[k][d]

    const int t  = threadIdx.x;
    const int tx = t & 15;
    const int ty = t >> 4;
    const int bh = blockIdx.y;
    const int b  = bh >> 4, h = bh & 15;
    const int q0 = blockIdx.x * 64;

    const size_t qtb = (size_t)bh * HD * SEQ;
    const int    c4  = tx * 4;

    #pragma unroll
    for (int n = 0; n < 4; n++) {
        const int d = ty + n * 16;
        float4 v = *(const float4*)&g_qT[qtb + (size_t)d * SEQ + q0 + c4];
        *(float4*)&sQ[d * 64 + c4] = v;
    }

    float4 kreg[4], vreg[4];
    #pragma unroll
    for (int n = 0; n < 4; n++) {
        const int r = ty + n * 16;
        kreg[n] = *(const float4*)&g_kT[qtb + (size_t)r * SEQ + 0 + c4];
        vreg[n] = *(const float4*)&g_qkv[(size_t)(b * SEQ + r) * TD + 2 * DMODEL + h * HD + c4];
    }

    float4 o4[4];
    #pragma unroll
    for (int i = 0; i < 4; i++) o4[i] = make_float4(0.f, 0.f, 0.f, 0.f);
    float m[4] = {-INFINITY, -INFINITY, -INFINITY, -INFINITY};
    float l[4] = {0.f, 0.f, 0.f, 0.f};

    for (int kt = 0; kt < SEQ / 64; kt++) {
        #pragma unroll
        for (int n = 0; n < 4; n++) {
            const int r = ty + n * 16;
            *(float4*)&sKP[r * 64 + c4] = kreg[n];
            *(float4*)&sV [r * 64 + c4] = vreg[n];
        }
        __syncthreads();

        if (kt + 1 < SEQ / 64) {
            const int k1 = (kt + 1) * 64;
            #pragma unroll
            for (int n = 0; n < 4; n++) {
                const int r = ty + n * 16;
                kreg[n] = *(const float4*)&g_kT[qtb + (size_t)r * SEQ + k1 + c4];
                vreg[n] = *(const float4*)&g_qkv[(size_t)(b * SEQ + k1 + r) * TD + 2 * DMODEL + h * HD + c4];
            }
        }

        float s[4][4];
        #pragma unroll
        for (int i = 0; i < 4; i++)
            #pragma unroll
            for (int j = 0; j < 4; j++) s[i][j] = 0.f;

        #pragma unroll 8
        for (int d = 0; d < 64; d++) {
            float4 qa = *(const float4*)&sQ [d * 64 + ty * 4];
            float4 kb = *(const float4*)&sKP[d * 64 + tx * 4];
            const float a[4] = {qa.x, qa.y, qa.z, qa.w};
            const float k[4] = {kb.x, kb.y, kb.z, kb.w};
            #pragma unroll
            for (int i = 0; i < 4; i++)
                #pragma unroll
                for (int j = 0; j < 4; j++)
                    s[i][j] += a[i] * k[j];
        }

        #pragma unroll
        for (int i = 0; i < 4; i++) {
            float mx = fmaxf(fmaxf(s[i][0], s[i][1]), fmaxf(s[i][2], s[i][3]));
            #pragma unroll
            for (int d = 1; d < 16; d <<= 1)
                mx = fmaxf(mx, __shfl_xor_sync(0xffffffffu, mx, d));
            const float mn = fmaxf(m[i], mx);
            const float al = __expf(m[i] - mn);
            m[i] = mn;
            float rs = 0.f;
            #pragma unroll
            for (int j = 0; j < 4; j++) {
                s[i][j] = __expf(s[i][j] - mn);
                rs += s[i][j];
            }
            #pragma unroll
            for (int d = 1; d < 16; d <<= 1)
                rs += __shfl_xor_sync(0xffffffffu, rs, d);
            l[i] = l[i] * al + rs;
            o4[i].x *= al; o4[i].y *= al; o4[i].z *= al; o4[i].w *= al;
        }

        __syncthreads();
        #pragma unroll
        for (int i = 0; i < 4; i++)
            *(float4*)&sKP[(ty * 4 + i) * 64 + tx * 4] =
                make_float4(s[i][0], s[i][1], s[i][2], s[i][3]);
        __syncthreads();

        #pragma unroll 4
        for (int j4 = 0; j4 < 16; j4++) {
            float4 vv0 = *(const float4*)&sV[(j4*4 + 0) * 64 + tx * 4];
            float4 vv1 = *(const float4*)&sV[(j4*4 + 1) * 64 + tx * 4];
            float4 vv2 = *(const float4*)&sV[(j4*4 + 2) * 64 + tx * 4];
            float4 vv3 = *(const float4*)&sV[(j4*4 + 3) * 64 + tx * 4];
            #pragma unroll
            for (int i = 0; i < 4; i++) {
                float4 p = *(const float4*)&sKP[(ty*4 + i) * 64 + j4 * 4];
                o4[i].x += p.x*vv0.x + p.y*vv1.x + p.z*vv2.x + p.w*vv3.x;
                o4[i].y += p.x*vv0.y + p.y*vv1.y + p.z*vv2.y + p.w*vv3.y;
                o4[i].z += p.x*vv0.z + p.y*vv1.z + p.z*vv2.z + p.w*vv3.z;
                o4[i].w += p.x*vv0.w + p.y*vv1.w + p.z*vv2.w + p.w*vv3.w;
            }
        }
        __syncthreads();
    }

    #pragma unroll
    for (int i = 0; i < 4; i++) {
        const float inv = 1.f / l[i];
        float4 v = o4[i];
        v.x *= inv; v.y *= inv; v.z *= inv; v.w *= inv;
        *(float4*)&g_attn[(size_t)(b * SEQ + q0 + ty*4 + i) * DMODEL + h * HD + tx * 4] = v;
    }
}

// ---------------------------------------------------------------------------
extern "C" void kernel_launch(void* const* d_in, const int* in_sizes, int n_in,
                              void* d_out, int out_size)
{
    const float* x     = (const float*)d_in[0];   // [4,2048,1024]
    const float* w_qkv = (const float*)d_in[1];   // [3072,1024]
    const float* w_out = (const float*)d_in[2];   // [1024,1024]
    const float* b_out = (const float*)d_in[3];   // [1024]
    float* out = (float*)d_out;                   // [4,2048,1024]

    // 1) QKV projection -> g_qkv   (mma.sync bf16x3)
    gemm1_tc<<<dim3(TD / 128, ROWS / 128), 256>>>(x, w_qkv);

    // 2) Per-head transpose of Q (scaled) and K -> g_qT / g_kT
    transpose_qk<<<dim3(SEQ / 32, 4, BATCH * NHEAD), dim3(32, 8)>>>();

    // 3) Flash attention -> g_attn in [B,N,D]
    attn_kernel<<<dim3(SEQ / 64, BATCH * NHEAD), 256>>>();

    // 4) Output projection + bias -> d_out   (mma.sync bf16x3)
    gemm2_tc<<<dim3(DMODEL / 128, ROWS / 128), 256>>>(w_out, b_out, out);
}

// round 12
// speedup vs baseline: 6.3266x; 1.7689x over previous
#include <cuda_runtime.h>
#include <cuda_bf16.h>
#include <math.h>
#include <stdint.h>

// Problem constants
#define BATCH   4
#define SEQ     2048
#define DMODEL  1024
#define NHEAD   16
#define HD      64
#define ROWS    (BATCH*SEQ)      // 8192
#define TD      (3*DMODEL)       // 3072
#define NBH     (BATCH*NHEAD)    // 64

// Scratch (__device__ globals; kernel_launch does nothing but launches)
__device__ float g_qkv[(size_t)ROWS * TD];              // [8192,3072] q|k|v
__device__ float g_attn[(size_t)ROWS * DMODEL];         // [8192,1024] attn out, [B,N,D]
// Per-head bf16 hi/lo operands, [bh][s][64] (Q pre-scaled by 1/8)
__device__ __nv_bfloat16 g_qhi[(size_t)NBH*SEQ*HD];
__device__ __nv_bfloat16 g_qlo[(size_t)NBH*SEQ*HD];
__device__ __nv_bfloat16 g_khi[(size_t)NBH*SEQ*HD];
__device__ __nv_bfloat16 g_klo[(size_t)NBH*SEQ*HD];
__device__ __nv_bfloat16 g_vhi[(size_t)NBH*SEQ*HD];
__device__ __nv_bfloat16 g_vlo[(size_t)NBH*SEQ*HD];

// ===========================================================================
// mma.sync helpers (base ISA; verified in R10)
// ===========================================================================
__device__ __forceinline__ uint32_t smem_u32(const void* p) {
    uint32_t a;
    asm("{ .reg .u64 t; cvta.to.shared.u64 t, %1; cvt.u32.u64 %0, t; }"
        : "=r"(a) : "l"(p));
    return a;
}

__device__ __forceinline__ void ldmatrix_x4(uint32_t& r0, uint32_t& r1,
                                            uint32_t& r2, uint32_t& r3,
                                            uint32_t addr) {
    asm volatile("ldmatrix.sync.aligned.m8n8.x4.shared.b16 {%0,%1,%2,%3}, [%4];"
                 : "=r"(r0), "=r"(r1), "=r"(r2), "=r"(r3) : "r"(addr));
}

__device__ __forceinline__ void ldmatrix_x2(uint32_t& r0, uint32_t& r1,
                                            uint32_t addr) {
    asm volatile("ldmatrix.sync.aligned.m8n8.x2.shared.b16 {%0,%1}, [%2];"
                 : "=r"(r0), "=r"(r1) : "r"(addr));
}

__device__ __forceinline__ void ldmatrix_x2t(uint32_t& r0, uint32_t& r1,
                                             uint32_t addr) {
    asm volatile("ldmatrix.sync.aligned.m8n8.x2.trans.shared.b16 {%0,%1}, [%2];"
                 : "=r"(r0), "=r"(r1) : "r"(addr));
}

__device__ __forceinline__ void mma_bf16(float* d, const uint32_t* a,
                                         const uint32_t* b) {
    asm volatile(
        "mma.sync.aligned.m16n8k16.row.col.f32.bf16.bf16.f32 "
        "{%0,%1,%2,%3}, {%4,%5,%6,%7}, {%8,%9}, {%0,%1,%2,%3};"
        : "+f"(d[0]), "+f"(d[1]), "+f"(d[2]), "+f"(d[3])
        : "r"(a[0]), "r"(a[1]), "r"(a[2]), "r"(a[3]), "r"(b[0]), "r"(b[1]));
}

// pack two fp32 -> bf16x2 (first arg lands in the LOW half = lower k index)
__device__ __forceinline__ uint32_t pack_bf16(float lo, float hi) {
    uint32_t r;
    asm("cvt.rn.bf16x2.f32 %0, %1, %2;" : "=r"(r) : "f"(hi), "f"(lo));
    return r;
}

// GEMM smem tile: 128 rows x 32 bf16 (64 B/row), 16B chunks XOR-swizzled
__device__ __forceinline__ uint32_t tile_off(int r, int c) {
    return (uint32_t)(r * 64 + (((c ^ ((r >> 1) & 3)) & 3) << 4));
}

// Attention smem tile: rows of 64 bf16 (128 B/row), 8 chunks, SW128-style
__device__ __forceinline__ uint32_t swz128(int r, int c) {
    return (uint32_t)(r * 128 + (((c ^ (r & 7)) & 7) << 4));
}

// split 16 fp32 -> bf16 hi + lo (two uint4 each)
__device__ __forceinline__ void split16(const float* v, uint4* hi, uint4* lo) {
    uint32_t h[8], l[8];
    #pragma unroll
    for (int p = 0; p < 8; p++) {
        float a = v[2*p], b = v[2*p+1];
        __nv_bfloat16 ha = __float2bfloat16_rn(a);
        __nv_bfloat16 hb = __float2bfloat16_rn(b);
        float ra = a - __bfloat162float(ha);
        float rb = b - __bfloat162float(hb);
        __nv_bfloat162 hh = __halves2bfloat162(ha, hb);
        __nv_bfloat162 ll = __halves2bfloat162(__float2bfloat16_rn(ra),
                                               __float2bfloat16_rn(rb));
        h[p] = *reinterpret_cast<uint32_t*>(&hh);
        l[p] = *reinterpret_cast<uint32_t*>(&ll);
    }
    hi[0] = make_uint4(h[0], h[1], h[2], h[3]);
    hi[1] = make_uint4(h[4], h[5], h[6], h[7]);
    lo[0] = make_uint4(l[0], l[1], l[2], l[3]);
    lo[1] = make_uint4(l[4], l[5], l[6], l[7]);
}

// split 8 fp32 -> bf16 hi + lo (one uint4 each)
__device__ __forceinline__ void split8v(const float* v, uint4& hi, uint4& lo) {
    uint32_t h[4], l[4];
    #pragma unroll
    for (int p = 0; p < 4; p++) {
        float a = v[2*p], b = v[2*p+1];
        __nv_bfloat16 ha = __float2bfloat16_rn(a);
        __nv_bfloat16 hb = __float2bfloat16_rn(b);
        float ra = a - __bfloat162float(ha);
        float rb = b - __bfloat162float(hb);
        __nv_bfloat162 hh = __halves2bfloat162(ha, hb);
        __nv_bfloat162 ll = __halves2bfloat162(__float2bfloat16_rn(ra),
                                               __float2bfloat16_rn(rb));
        h[p] = *reinterpret_cast<uint32_t*>(&hh);
        l[p] = *reinterpret_cast<uint32_t*>(&ll);
    }
    hi = make_uint4(h[0], h[1], h[2], h[3]);
    lo = make_uint4(l[0], l[1], l[2], l[3]);
}

// ===========================================================================
// Tensor-core GEMM (bf16x3, mma.sync): C[M,N] = A[M,K] @ B[N,K]^T (+bias).
// 128x128 CTA tile, BK=32, 256 threads (8 warps, 2m x 4n). Verified R10.
// ===========================================================================
__device__ __forceinline__ void gemm_mma_body(
    const float* __restrict__ A, const float* __restrict__ B,
    const float* __restrict__ bias, float* __restrict__ C,
    int M, int N, int K)
{
    __shared__ uint8_t sAhi[8192], sAlo[8192], sBhi[8192], sBlo[8192];

    const int t    = threadIdx.x;
    const int lane = t & 31;
    const int wid  = t >> 5;
    const int wm   = wid & 1;
    const int wn   = wid >> 1;
    const int m0   = blockIdx.y * 128;
    const int n0   = blockIdx.x * 128;

    const uint32_t bAhi = smem_u32(sAhi), bAlo = smem_u32(sAlo);
    const uint32_t bBhi = smem_u32(sBhi), bBlo = smem_u32(sBlo);

    const int sr = t >> 1;
    const int sh = t & 1;
    const uint32_t so0 = tile_off(sr, sh * 2);
    const uint32_t so1 = tile_off(sr, sh * 2 + 1);
    const float* Ap = A + (size_t)(m0 + sr) * K + sh * 16;
    const float* Bp = B + (size_t)(n0 + sr) * K + sh * 16;

    const int arow = wm * 64 + (lane & 15);
    const int acol_lane = lane >> 4;
    const int brow = wn * 32 + (lane & 7);
    const int bcol_lane = (lane >> 3) & 1;

    float d[4][4][4];
    #pragma unroll
    for (int mt = 0; mt < 4; mt++)
        #pragma unroll
        for (int nt = 0; nt < 4; nt++)
            #pragma unroll
            for (int e = 0; e < 4; e++) d[mt][nt][e] = 0.f;

    float va[16], vb[16];
    #pragma unroll
    for (int q = 0; q < 4; q++) {
        *(float4*)&va[q*4] = *(const float4*)(Ap + q*4);
        *(float4*)&vb[q*4] = *(const float4*)(Bp + q*4);
    }

    const int nchunk = K >> 5;
    for (int c = 0; c < nchunk; c++) {
        uint4 hi[2], lo[2];
        split16(va, hi, lo);
        *(uint4*)(sAhi + so0) = hi[0]; *(uint4*)(sAhi + so1) = hi[1];
        *(uint4*)(sAlo + so0) = lo[0]; *(uint4*)(sAlo + so1) = lo[1];
        split16(vb, hi, lo);
        *(uint4*)(sBhi + so0) = hi[0]; *(uint4*)(sBhi + so1) = hi[1];
        *(uint4*)(sBlo + so0) = lo[0]; *(uint4*)(sBlo + so1) = lo[1];
        __syncthreads();

        if (c + 1 < nchunk) {
            const float* An = Ap + (c + 1) * 32;
            const float* Bn = Bp + (c + 1) * 32;
            #pragma unroll
            for (int q = 0; q < 4; q++) {
                *(float4*)&va[q*4] = *(const float4*)(An + q*4);
                *(float4*)&vb[q*4] = *(const float4*)(Bn + q*4);
            }
        }

        #pragma unroll
        for (int ks = 0; ks < 2; ks++) {
            uint32_t a_hi[4][4], a_lo[4][4], b_hi[4][2], b_lo[4][2];
            #pragma unroll
            for (int mt = 0; mt < 4; mt++) {
                const uint32_t off = tile_off(arow + mt * 16, ks * 2 + acol_lane);
                ldmatrix_x4(a_hi[mt][0], a_hi[mt][1], a_hi[mt][2], a_hi[mt][3], bAhi + off);
                ldmatrix_x4(a_lo[mt][0], a_lo[mt][1], a_lo[mt][2], a_lo[mt][3], bAlo + off);
            }
            #pragma unroll
            for (int nt = 0; nt < 4; nt++) {
                const uint32_t off = tile_off(brow + nt * 8, ks * 2 + bcol_lane);
                ldmatrix_x2(b_hi[nt][0], b_hi[nt][1], bBhi + off);
                ldmatrix_x2(b_lo[nt][0], b_lo[nt][1], bBlo + off);
            }
            #pragma unroll
            for (int mt = 0; mt < 4; mt++)
                #pragma unroll
                for (int nt = 0; nt < 4; nt++) {
                    mma_bf16(d[mt][nt], a_hi[mt], b_hi[nt]);
                    mma_bf16(d[mt][nt], a_hi[mt], b_lo[nt]);
                    mma_bf16(d[mt][nt], a_lo[mt], b_hi[nt]);
                }
        }
        __syncthreads();
    }

    const int er = lane >> 2;
    const int ec = (lane & 3) * 2;
    #pragma unroll
    for (int nt = 0; nt < 4; nt++) {
        const int col = n0 + wn * 32 + nt * 8 + ec;
        float bx = 0.f, by = 0.f;
        if (bias) { bx = bias[col]; by = bias[col + 1]; }
        #pragma unroll
        for (int mt = 0; mt < 4; mt++) {
            const int row = m0 + wm * 64 + mt * 16 + er;
            float2 lo2 = make_float2(d[mt][nt][0] + bx, d[mt][nt][1] + by);
            float2 hi2 = make_float2(d[mt][nt][2] + bx, d[mt][nt][3] + by);
            *(float2*)&C[(size_t)row * N + col]       = lo2;
            *(float2*)&C[(size_t)(row + 8) * N + col] = hi2;
        }
    }
}

__global__ __launch_bounds__(256) void gemm1_tc(const float* __restrict__ x,
                                                const float* __restrict__ w)
{
    gemm_mma_body(x, w, nullptr, g_qkv, ROWS, TD, DMODEL);
}

__global__ __launch_bounds__(256) void gemm2_tc(const float* __restrict__ w,
                                                const float* __restrict__ bias,
                                                float* __restrict__ out)
{
    gemm_mma_body(g_attn, w, bias, out, ROWS, DMODEL, DMODEL);
}

// ---------------------------------------------------------------------------
// Convert: gather per-head Q/K/V from g_qkv, split to bf16 hi/lo, [bh][s][64].
// Q pre-scaled by 0.125. One thread = 8 d-elements of one (bh, s).
// ---------------------------------------------------------------------------
__global__ __launch_bounds__(256) void convert_qkv()
{
    const int idx = blockIdx.x * 256 + threadIdx.x;
    const int u   = idx & 7;               // d-chunk of 8
    const int s   = (idx >> 3) & 2047;
    const int bh  = idx >> 14;
    const int b   = bh >> 4, h = bh & 15;
    const int d0  = u * 8;

    const size_t src = (size_t)(b * SEQ + s) * TD + h * HD + d0;
    const size_t dst = ((size_t)(bh * SEQ + s) * HD + d0) / 8;  // uint4 index

    float v[8];
    uint4 hi, lo;

    // Q (scaled)
    *(float4*)&v[0] = *(const float4*)&g_qkv[src];
    *(float4*)&v[4] = *(const float4*)&g_qkv[src + 4];
    #pragma unroll
    for (int i = 0; i < 8; i++) v[i] *= 0.125f;
    split8v(v, hi, lo);
    ((uint4*)g_qhi)[dst] = hi;  ((uint4*)g_qlo)[dst] = lo;

    // K
    *(float4*)&v[0] = *(const float4*)&g_qkv[src + DMODEL];
    *(float4*)&v[4] = *(const float4*)&g_qkv[src + DMODEL + 4];
    split8v(v, hi, lo);
    ((uint4*)g_khi)[dst] = hi;  ((uint4*)g_klo)[dst] = lo;

    // V
    *(float4*)&v[0] = *(const float4*)&g_qkv[src + 2*DMODEL];
    *(float4*)&v[4] = *(const float4*)&g_qkv[src + 2*DMODEL + 4];
    split8v(v, hi, lo);
    ((uint4*)g_vhi)[dst] = hi;  ((uint4*)g_vlo)[dst] = lo;
}

// ---------------------------------------------------------------------------
// Flash attention on tensor cores (mma.sync bf16x3).
// Block: 256 thr = 8 warps; q-tile 128 (16 rows/warp); k-tiles of 64.
// S = Q@K^T (3 terms), softmax warp-local, P reused as a-frag from c-frag,
// PV (3 terms) with ldmatrix.trans V loads. Output -> g_attn [B,N,D].
// grid (SEQ/128 = 16, NBH = 64)
// ---------------------------------------------------------------------------
__global__ __launch_bounds__(256) void attn_mma()
{
    // union: phase A = Qhi(16K)+Qlo(16K); phase B = Khi/Klo/Vhi/Vlo (8K each)
    __shared__ __align__(128) uint8_t sbuf[32768];

    const int t    = threadIdx.x;
    const int lane = t & 31;
    const int wq   = t >> 5;                 // warp -> q rows wq*16..+15
    const int bh   = blockIdx.y;
    const int b    = bh >> 4, h = bh & 15;
    const int q0   = blockIdx.x * 128;

    const uint32_t sB   = smem_u32(sbuf);
    const uint32_t sKhi = sB, sKlo = sB + 8192, sVhi = sB + 16384, sVlo = sB + 24576;
    const uint32_t sQhi = sB, sQlo = sB + 16384;

    const size_t headbase = (size_t)bh * SEQ * HD;   // element offset in bf16 arrays

    // ---- Phase A: stage Q, load persistent a-frags ----
    #pragma unroll
    for (int u = 0; u < 4; u++) {
        const int i   = t * 4 + u;        // 0..1023
        const int row = i >> 3;           // 0..127
        const int ch  = i & 7;
        const uint32_t so = swz128(row, ch);
        const size_t g = (headbase + (size_t)(q0 + row) * HD + ch * 8) / 8;
        *(uint4*)(sbuf + (sQhi - sB) + so) = ((const uint4*)g_qhi)[g];
        *(uint4*)(sbuf + (sQlo - sB) + so) = ((const uint4*)g_qlo)[g];
    }
    __syncthreads();

    uint32_t qhi[4][4], qlo[4][4];
    {
        const int arow = wq * 16 + (lane & 15);
        const int acl  = lane >> 4;
        #pragma unroll
        for (int ks = 0; ks < 4; ks++) {
            const uint32_t off = swz128(arow, ks * 2 + acl);
            ldmatrix_x4(qhi[ks][0], qhi[ks][1], qhi[ks][2], qhi[ks][3], sQhi + off);
            ldmatrix_x4(qlo[ks][0], qlo[ks][1], qlo[ks][2], qlo[ks][3], sQlo + off);
        }
    }
    __syncthreads();   // Q smem no longer needed

    // ---- per-thread frag coordinates ----
    const int er  = lane >> 2;                // c-frag row (and +8)
    const int ec  = (lane & 3) * 2;           // c-frag col pair base
    const int kbr = lane & 7;                 // K b-frag row lane
    const int kbc = (lane >> 3) & 1;          // K b-frag chunk lane
    const int vbr = lane & 15;                // V b-frag (trans) row lane

    // staging map for K/V tiles: 2 uint4 per array per thread
    const int si0 = t * 2, si1 = t * 2 + 1;
    const uint32_t kso0 = swz128(si0 >> 3, si0 & 7);
    const uint32_t kso1 = swz128(si1 >> 3, si1 & 7);

    // online-softmax state + O accumulators
    float m0 = -INFINITY, m1 = -INFINITY, l0 = 0.f, l1 = 0.f;
    float o[8][4];
    #pragma unroll
    for (int dt = 0; dt < 8; dt++)
        #pragma unroll
        for (int e = 0; e < 4; e++) o[dt][e] = 0.f;

    // prefetch tile 0
    uint4 pf[8];
    {
        const size_t g0 = (headbase + (size_t)(si0 >> 3) * HD + (si0 & 7) * 8) / 8;
        const size_t g1 = (headbase + (size_t)(si1 >> 3) * HD + (si1 & 7) * 8) / 8;
        pf[0] = ((const uint4*)g_khi)[g0]; pf[1] = ((const uint4*)g_khi)[g1];
        pf[2] = ((const uint4*)g_klo)[g0]; pf[3] = ((const uint4*)g_klo)[g1];
        pf[4] = ((const uint4*)g_vhi)[g0]; pf[5] = ((const uint4*)g_vhi)[g1];
        pf[6] = ((const uint4*)g_vlo)[g0]; pf[7] = ((const uint4*)g_vlo)[g1];
    }

    for (int kt = 0; kt < SEQ / 64; kt++) {
        // commit staged tile
        *(uint4*)(sbuf + 0     + kso0) = pf[0]; *(uint4*)(sbuf + 0     + kso1) = pf[1];
        *(uint4*)(sbuf + 8192  + kso0) = pf[2]; *(uint4*)(sbuf + 8192  + kso1) = pf[3];
        *(uint4*)(sbuf + 16384 + kso0) = pf[4]; *(uint4*)(sbuf + 16384 + kso1) = pf[5];
        *(uint4*)(sbuf + 24576 + kso0) = pf[6]; *(uint4*)(sbuf + 24576 + kso1) = pf[7];
        __syncthreads();

        if (kt + 1 < SEQ / 64) {
            const size_t kb = headbase + (size_t)(kt + 1) * 64 * HD;
            const size_t g0 = (kb + (size_t)(si0 >> 3) * HD + (si0 & 7) * 8) / 8;
            const size_t g1 = (kb + (size_t)(si1 >> 3) * HD + (si1 & 7) * 8) / 8;
            pf[0] = ((const uint4*)g_khi)[g0]; pf[1] = ((const uint4*)g_khi)[g1];
            pf[2] = ((const uint4*)g_klo)[g0]; pf[3] = ((const uint4*)g_klo)[g1];
            pf[4] = ((const uint4*)g_vhi)[g0]; pf[5] = ((const uint4*)g_vhi)[g1];
            pf[6] = ((const uint4*)g_vlo)[g0]; pf[7] = ((const uint4*)g_vlo)[g1];
        }

        // ---- S = Q @ K^T  (8 n-tiles of 8 keys), bf16x3 ----
        float s[8][4];
        #pragma unroll
        for (int nt = 0; nt < 8; nt++)
            #pragma unroll
            for (int e = 0; e < 4; e++) s[nt][e] = 0.f;

        #pragma unroll
        for (int ks = 0; ks < 4; ks++) {
            #pragma unroll
            for (int nt = 0; nt < 8; nt++) {
                uint32_t bhh[2], bll[2];
                const uint32_t off = swz128(nt * 8 + kbr, ks * 2 + kbc);
                ldmatrix_x2(bhh[0], bhh[1], sKhi + off);
                ldmatrix_x2(bll[0], bll[1], sKlo + off);
                mma_bf16(s[nt], qhi[ks], bhh);
                mma_bf16(s[nt], qhi[ks], bll);
                mma_bf16(s[nt], qlo[ks], bhh);
            }
        }

        // ---- online softmax (rows er and er+8; reduce over lane&3 group) ----
        float mx0 = s[0][0], mx1 = s[0][2];
        #pragma unroll
        for (int nt = 0; nt < 8; nt++) {
            mx0 = fmaxf(mx0, fmaxf(s[nt][0], s[nt][1]));
            mx1 = fmaxf(mx1, fmaxf(s[nt][2], s[nt][3]));
        }
        mx0 = fmaxf(mx0, __shfl_xor_sync(0xffffffffu, mx0, 1));
        mx0 = fmaxf(mx0, __shfl_xor_sync(0xffffffffu, mx0, 2));
        mx1 = fmaxf(mx1, __shfl_xor_sync(0xffffffffu, mx1, 1));
        mx1 = fmaxf(mx1, __shfl_xor_sync(0xffffffffu, mx1, 2));

        const float mn0 = fmaxf(m0, mx0);
        const float mn1 = fmaxf(m1, mx1);
        const float al0 = __expf(m0 - mn0);
        const float al1 = __expf(m1 - mn1);
        m0 = mn0; m1 = mn1;

        float rs0 = 0.f, rs1 = 0.f;
        #pragma unroll
        for (int nt = 0; nt < 8; nt++) {
            s[nt][0] = __expf(s[nt][0] - mn0);
            s[nt][1] = __expf(s[nt][1] - mn0);
            s[nt][2] = __expf(s[nt][2] - mn1);
            s[nt][3] = __expf(s[nt][3] - mn1);
            rs0 += s[nt][0] + s[nt][1];
            rs1 += s[nt][2] + s[nt][3];
        }
        rs0 += __shfl_xor_sync(0xffffffffu, rs0, 1);
        rs0 += __shfl_xor_sync(0xffffffffu, rs0, 2);
        rs1 += __shfl_xor_sync(0xffffffffu, rs1, 1);
        rs1 += __shfl_xor_sync(0xffffffffu, rs1, 2);
        l0 = l0 * al0 + rs0;
        l1 = l1 * al1 + rs1;

        #pragma unroll
        for (int dt = 0; dt < 8; dt++) {
            o[dt][0] *= al0; o[dt][1] *= al0;
            o[dt][2] *= al1; o[dt][3] *= al1;
        }

        // ---- pack P into a-frags (hi + lo residual), direct from c-frags ----
        uint32_t pa_hi[4][4], pa_lo[4][4];
        #pragma unroll
        for (int kk = 0; kk < 4; kk++) {
            #pragma unroll
            for (int half = 0; half < 2; half++) {     // S tile 2kk, 2kk+1
                const float* sv = s[2*kk + half];
                float rh[4], rl[4];
                #pragma unroll
                for (int e = 0; e < 4; e++) {
                    __nv_bfloat16 hh = __float2bfloat16_rn(sv[e]);
                    rh[e] = __bfloat162float(hh);
                    rl[e] = sv[e] - rh[e];
                }
                pa_hi[kk][half*2 + 0] = pack_bf16(rh[0], rh[1]);
                pa_hi[kk][half*2 + 1] = pack_bf16(rh[2], rh[3]);
                pa_lo[kk][half*2 + 0] = pack_bf16(rl[0], rl[1]);
                pa_lo[kk][half*2 + 1] = pack_bf16(rl[2], rl[3]);
            }
        }

        // ---- O += P @ V  (8 d-tiles), bf16x3, V via ldmatrix.trans ----
        #pragma unroll
        for (int kk = 0; kk < 4; kk++) {
            #pragma unroll
            for (int dt = 0; dt < 8; dt++) {
                uint32_t bvh[2], bvl[2];
                const uint32_t off = swz128(kk * 16 + vbr, dt);
                ldmatrix_x2t(bvh[0], bvh[1], sVhi + off);
                ldmatrix_x2t(bvl[0], bvl[1], sVlo + off);
                mma_bf16(o[dt], pa_hi[kk], bvh);
                mma_bf16(o[dt], pa_hi[kk], bvl);
                mma_bf16(o[dt], pa_lo[kk], bvh);
            }
        }
        __syncthreads();   // tile reads done before next staging
    }

    // ---- epilogue: normalize, write g_attn [B,N,D] ----
    const float inv0 = 1.f / l0;
    const float inv1 = 1.f / l1;
    const int row0 = b * SEQ + q0 + wq * 16 + er;
    #pragma unroll
    for (int dt = 0; dt < 8; dt++) {
        const int col = h * HD + dt * 8 + ec;
        *(float2*)&g_attn[(size_t)row0 * DMODEL + col] =
            make_float2(o[dt][0] * inv0, o[dt][1] * inv0);
        *(float2*)&g_attn[(size_t)(row0 + 8) * DMODEL + col] =
            make_float2(o[dt][2] * inv1, o[dt][3] * inv1);
    }
}

// ---------------------------------------------------------------------------
extern "C" void kernel_launch(void* const* d_in, const int* in_sizes, int n_in,
                              void* d_out, int out_size)
{
    const float* x     = (const float*)d_in[0];   // [4,2048,1024]
    const float* w_qkv = (const float*)d_in[1];   // [3072,1024]
    const float* w_out = (const float*)d_in[2];   // [1024,1024]
    const float* b_out = (const float*)d_in[3];   // [1024]
    float* out = (float*)d_out;                   // [4,2048,1024]

    // 1) QKV projection -> g_qkv   (mma.sync bf16x3)
    gemm1_tc<<<dim3(TD / 128, ROWS / 128), 256>>>(x, w_qkv);

    // 2) Gather + bf16 hi/lo split of per-head Q (scaled), K, V
    convert_qkv<<<4096, 256>>>();

    // 3) Flash attention on tensor cores -> g_attn [B,N,D]
    attn_mma<<<dim3(SEQ / 128, NBH), 256>>>();

    // 4) Output projection + bias -> d_out   (mma.sync bf16x3)
    gemm2_tc<<<dim3(DMODEL / 128, ROWS / 128), 256>>>(w_out, b_out, out);
}

// round 16
// speedup vs baseline: 6.7816x; 1.0719x over previous
#include <cuda_runtime.h>
#include <cuda_bf16.h>
#include <math.h>
#include <stdint.h>

// Problem constants
#define BATCH   4
#define SEQ     2048
#define DMODEL  1024
#define NHEAD   16
#define HD      64
#define ROWS    (BATCH*SEQ)      // 8192
#define TD      (3*DMODEL)       // 3072
#define NBH     (BATCH*NHEAD)    // 64

// Scratch (__device__ globals; addresses NEVER passed from host — ATS makes
// host-shadow writes silently succeed on GB300, see R14/R15 post-mortem)
__device__ __nv_bfloat16 g_xhi[(size_t)ROWS*DMODEL],  g_xlo[(size_t)ROWS*DMODEL];
__device__ __nv_bfloat16 g_w1hi[(size_t)TD*DMODEL],   g_w1lo[(size_t)TD*DMODEL];
__device__ __nv_bfloat16 g_w2hi[(size_t)DMODEL*DMODEL], g_w2lo[(size_t)DMODEL*DMODEL];
// Per-head q/k/v (written by gemm1 epilogue; Q pre-scaled by 1/8), [bh][s][64]
__device__ __nv_bfloat16 g_qhi[(size_t)NBH*SEQ*HD], g_qlo[(size_t)NBH*SEQ*HD];
__device__ __nv_bfloat16 g_khi[(size_t)NBH*SEQ*HD], g_klo[(size_t)NBH*SEQ*HD];
__device__ __nv_bfloat16 g_vhi[(size_t)NBH*SEQ*HD], g_vlo[(size_t)NBH*SEQ*HD];
// Attention output, bf16 hi/lo, [B*N, D]
__device__ __nv_bfloat16 g_ahi[(size_t)ROWS*DMODEL], g_alo[(size_t)ROWS*DMODEL];

// ===========================================================================
// helpers (base ISA; fragment mappings verified R10/R12)
// ===========================================================================
__device__ __forceinline__ uint32_t smem_u32(const void* p) {
    uint32_t a;
    asm("{ .reg .u64 t; cvta.to.shared.u64 t, %1; cvt.u32.u64 %0, t; }"
        : "=r"(a) : "l"(p));
    return a;
}

__device__ __forceinline__ void ldmatrix_x4(uint32_t& r0, uint32_t& r1,
                                            uint32_t& r2, uint32_t& r3,
                                            uint32_t addr) {
    asm volatile("ldmatrix.sync.aligned.m8n8.x4.shared.b16 {%0,%1,%2,%3}, [%4];"
                 : "=r"(r0), "=r"(r1), "=r"(r2), "=r"(r3) : "r"(addr));
}

__device__ __forceinline__ void ldmatrix_x2(uint32_t& r0, uint32_t& r1,
                                            uint32_t addr) {
    asm volatile("ldmatrix.sync.aligned.m8n8.x2.shared.b16 {%0,%1}, [%2];"
                 : "=r"(r0), "=r"(r1) : "r"(addr));
}

__device__ __forceinline__ void ldmatrix_x2t(uint32_t& r0, uint32_t& r1,
                                             uint32_t addr) {
    asm volatile("ldmatrix.sync.aligned.m8n8.x2.trans.shared.b16 {%0,%1}, [%2];"
                 : "=r"(r0), "=r"(r1) : "r"(addr));
}

__device__ __forceinline__ void mma_bf16(float* d, const uint32_t* a,
                                         const uint32_t* b) {
    asm volatile(
        "mma.sync.aligned.m16n8k16.row.col.f32.bf16.bf16.f32 "
        "{%0,%1,%2,%3}, {%4,%5,%6,%7}, {%8,%9}, {%0,%1,%2,%3};"
        : "+f"(d[0]), "+f"(d[1]), "+f"(d[2]), "+f"(d[3])
        : "r"(a[0]), "r"(a[1]), "r"(a[2]), "r"(a[3]), "r"(b[0]), "r"(b[1]));
}

// pack two fp32 -> bf16x2 (first arg lands in the LOW half)
__device__ __forceinline__ uint32_t pack_bf16(float lo, float hi) {
    uint32_t r;
    asm("cvt.rn.bf16x2.f32 %0, %1, %2;" : "=r"(r) : "f"(hi), "f"(lo));
    return r;
}

// GEMM smem tile: 128 rows x 32 bf16 (64 B/row), 16B chunks XOR-swizzled
__device__ __forceinline__ uint32_t tile_off(int r, int c) {
    return (uint32_t)(r * 64 + (((c ^ ((r >> 1) & 3)) & 3) << 4));
}

// Attention smem tile: rows of 64 bf16 (128 B/row), 8 chunks, SW128-style
__device__ __forceinline__ uint32_t swz128(int r, int c) {
    return (uint32_t)(r * 128 + (((c ^ (r & 7)) & 7) << 4));
}

// split 8 fp32 -> bf16 hi + lo (one uint4 each)
__device__ __forceinline__ void split8v(const float* v, uint4& hi, uint4& lo) {
    uint32_t h[4], l[4];
    #pragma unroll
    for (int p = 0; p < 4; p++) {
        float a = v[2*p], b = v[2*p+1];
        __nv_bfloat16 ha = __float2bfloat16_rn(a);
        __nv_bfloat16 hb = __float2bfloat16_rn(b);
        float ra = a - __bfloat162float(ha);
        float rb = b - __bfloat162float(hb);
        __nv_bfloat162 hh = __halves2bfloat162(ha, hb);
        __nv_bfloat162 ll = __halves2bfloat162(__float2bfloat16_rn(ra),
                                               __float2bfloat16_rn(rb));
        h[p] = *reinterpret_cast<uint32_t*>(&hh);
        l[p] = *reinterpret_cast<uint32_t*>(&ll);
    }
    hi = make_uint4(h[0], h[1], h[2], h[3]);
    lo = make_uint4(l[0], l[1], l[2], l[3]);
}

// split one fp32 pair -> hi uint32 + lo uint32
__device__ __forceinline__ void split2(float a, float b, uint32_t& hi, uint32_t& lo) {
    __nv_bfloat16 ha = __float2bfloat16_rn(a);
    __nv_bfloat16 hb = __float2bfloat16_rn(b);
    __nv_bfloat162 hh = __halves2bfloat162(ha, hb);
    hi = *reinterpret_cast<uint32_t*>(&hh);
    float ra = a - __bfloat162float(ha);
    float rb = b - __bfloat162float(hb);
    __nv_bfloat162 ll = __halves2bfloat162(__float2bfloat16_rn(ra),
                                           __float2bfloat16_rn(rb));
    lo = *reinterpret_cast<uint32_t*>(&ll);
}

// ---------------------------------------------------------------------------
// presplit: fp32 array -> bf16 hi/lo GLOBALS (bound in device code — the
// destination must NOT be a host-passed __device__-symbol pointer).
// ---------------------------------------------------------------------------
__device__ __forceinline__ void presplit_body(const float* __restrict__ s,
                                              __nv_bfloat16* __restrict__ hi,
                                              __nv_bfloat16* __restrict__ lo)
{
    const size_t i = ((size_t)blockIdx.x * 256 + threadIdx.x) * 8;
    float v[8];
    *(float4*)&v[0] = *(const float4*)&s[i];
    *(float4*)&v[4] = *(const float4*)&s[i + 4];
    uint4 h, l;
    split8v(v, h, l);
    *(uint4*)&hi[i] = h;
    *(uint4*)&lo[i] = l;
}

__global__ __launch_bounds__(256) void presplit_x(const float* __restrict__ s)
{ presplit_body(s, g_xhi, g_xlo); }

__global__ __launch_bounds__(256) void presplit_w1(const float* __restrict__ s)
{ presplit_body(s, g_w1hi, g_w1lo); }

__global__ __launch_bounds__(256) void presplit_w2(const float* __restrict__ s)
{ presplit_body(s, g_w2hi, g_w2lo); }

// ===========================================================================
// Tensor-core GEMM mainloop — EXACT R10-verified structure (256 thr, 8 warps
// 2m x 4n, warp tile 64x32, BK=32, static smem, register prefetch).
// Operands arrive pre-split (8 uint4 LDGs, no split math in hot loop).
// ===========================================================================
__device__ __forceinline__ void gemm_mainloop(
    const __nv_bfloat16* __restrict__ Ahi, const __nv_bfloat16* __restrict__ Alo,
    const __nv_bfloat16* __restrict__ Bhi, const __nv_bfloat16* __restrict__ Blo,
    int m0, int n0, int K, float d[4][4][4])
{
    __shared__ uint8_t sAhi[8192], sAlo[8192], sBhi[8192], sBlo[8192];

    const int t    = threadIdx.x;
    const int lane = t & 31;
    const int wid  = t >> 5;
    const int wm   = wid & 1;
    const int wn   = wid >> 1;

    const uint32_t bAhi = smem_u32(sAhi), bAlo = smem_u32(sAlo);
    const uint32_t bBhi = smem_u32(sBhi), bBlo = smem_u32(sBlo);

    const int sr = t >> 1;
    const int sh = t & 1;
    const uint32_t so0 = tile_off(sr, sh * 2);
    const uint32_t so1 = tile_off(sr, sh * 2 + 1);
    const size_t abase = (size_t)(m0 + sr) * K + sh * 16;
    const size_t bbase = (size_t)(n0 + sr) * K + sh * 16;

    const int arow = wm * 64 + (lane & 15);
    const int acol_lane = lane >> 4;
    const int brow = wn * 32 + (lane & 7);
    const int bcol_lane = (lane >> 3) & 1;

    #pragma unroll
    for (int mt = 0; mt < 4; mt++)
        #pragma unroll
        for (int nt = 0; nt < 4; nt++)
            #pragma unroll
            for (int e = 0; e < 4; e++) d[mt][nt][e] = 0.f;

    uint4 pAh0 = *(const uint4*)(Ahi + abase);
    uint4 pAh1 = *(const uint4*)(Ahi + abase + 8);
    uint4 pAl0 = *(const uint4*)(Alo + abase);
    uint4 pAl1 = *(const uint4*)(Alo + abase + 8);
    uint4 pBh0 = *(const uint4*)(Bhi + bbase);
    uint4 pBh1 = *(const uint4*)(Bhi + bbase + 8);
    uint4 pBl0 = *(const uint4*)(Blo + bbase);
    uint4 pBl1 = *(const uint4*)(Blo + bbase + 8);

    const int nchunk = K >> 5;
    for (int c = 0; c < nchunk; c++) {
        *(uint4*)(sAhi + so0) = pAh0; *(uint4*)(sAhi + so1) = pAh1;
        *(uint4*)(sAlo + so0) = pAl0; *(uint4*)(sAlo + so1) = pAl1;
        *(uint4*)(sBhi + so0) = pBh0; *(uint4*)(sBhi + so1) = pBh1;
        *(uint4*)(sBlo + so0) = pBl0; *(uint4*)(sBlo + so1) = pBl1;
        __syncthreads();

        if (c + 1 < nchunk) {
            const int k1 = (c + 1) * 32;
            pAh0 = *(const uint4*)(Ahi + abase + k1);
            pAh1 = *(const uint4*)(Ahi + abase + k1 + 8);
            pAl0 = *(const uint4*)(Alo + abase + k1);
            pAl1 = *(const uint4*)(Alo + abase + k1 + 8);
            pBh0 = *(const uint4*)(Bhi + bbase + k1);
            pBh1 = *(const uint4*)(Bhi + bbase + k1 + 8);
            pBl0 = *(const uint4*)(Blo + bbase + k1);
            pBl1 = *(const uint4*)(Blo + bbase + k1 + 8);
        }

        #pragma unroll
        for (int ks = 0; ks < 2; ks++) {
            uint32_t a_hi[4][4], a_lo[4][4], b_hi[4][2], b_lo[4][2];
            #pragma unroll
            for (int mt = 0; mt < 4; mt++) {
                const uint32_t off = tile_off(arow + mt * 16, ks * 2 + acol_lane);
                ldmatrix_x4(a_hi[mt][0], a_hi[mt][1], a_hi[mt][2], a_hi[mt][3], bAhi + off);
                ldmatrix_x4(a_lo[mt][0], a_lo[mt][1], a_lo[mt][2], a_lo[mt][3], bAlo + off);
            }
            #pragma unroll
            for (int nt = 0; nt < 4; nt++) {
                const uint32_t off = tile_off(brow + nt * 8, ks * 2 + bcol_lane);
                ldmatrix_x2(b_hi[nt][0], b_hi[nt][1], bBhi + off);
                ldmatrix_x2(b_lo[nt][0], b_lo[nt][1], bBlo + off);
            }
            #pragma unroll
            for (int mt = 0; mt < 4; mt++)
                #pragma unroll
                for (int nt = 0; nt < 4; nt++) {
                    mma_bf16(d[mt][nt], a_hi[mt], b_hi[nt]);
                    mma_bf16(d[mt][nt], a_hi[mt], b_lo[nt]);
                    mma_bf16(d[mt][nt], a_lo[mt], b_hi[nt]);
                }
        }
        __syncthreads();
    }
}

// GEMM1: qkv projection; fused epilogue scatters bf16 hi/lo q/k/v per head.
__global__ __launch_bounds__(256) void gemm1_tc()
{
    float d[4][4][4];
    const int m0 = blockIdx.y * 128;
    const int n0 = blockIdx.x * 128;
    gemm_mainloop(g_xhi, g_xlo, g_w1hi, g_w1lo, m0, n0, DMODEL, d);

    const int lane = threadIdx.x & 31;
    const int wid  = threadIdx.x >> 5;
    const int wm   = wid & 1;
    const int wn   = wid >> 1;
    const int er   = lane >> 2;
    const int ec   = (lane & 3) * 2;

    #pragma unroll
    for (int nt = 0; nt < 4; nt++) {
        const int col  = n0 + wn * 32 + nt * 8 + ec;    // 0..3071
        const int part = col >> 10;                      // 0=q 1=k 2=v
        const int h    = (col & 1023) >> 6;
        const int dd   = col & 63;
        __nv_bfloat16 *ph, *pl;
        float scale;
        if (part == 0)      { ph = g_qhi; pl = g_qlo; scale = 0.125f; }
        else if (part == 1) { ph = g_khi; pl = g_klo; scale = 1.0f; }
        else                { ph = g_vhi; pl = g_vlo; scale = 1.0f; }

        #pragma unroll
        for (int mt = 0; mt < 4; mt++) {
            #pragma unroll
            for (int hf = 0; hf < 2; hf++) {
                const int row = m0 + wm * 64 + mt * 16 + er + hf * 8;
                const int b   = row >> 11;               // row / SEQ
                const int s   = row & 2047;
                const size_t off = ((size_t)((b * 16 + h) * SEQ + s)) * HD + dd;
                uint32_t uh, ul;
                split2(d[mt][nt][hf*2 + 0] * scale, d[mt][nt][hf*2 + 1] * scale, uh, ul);
                *(uint32_t*)&ph[off] = uh;
                *(uint32_t*)&pl[off] = ul;
            }
        }
    }
}

// GEMM2: output projection + bias, fp32 out (R10-verified epilogue geometry).
__global__ __launch_bounds__(256) void gemm2_tc(const float* __restrict__ bias,
                                                float* __restrict__ out)
{
    float d[4][4][4];
    const int m0 = blockIdx.y * 128;
    const int n0 = blockIdx.x * 128;
    gemm_mainloop(g_ahi, g_alo, g_w2hi, g_w2lo, m0, n0, DMODEL, d);

    const int lane = threadIdx.x & 31;
    const int wid  = threadIdx.x >> 5;
    const int wm   = wid & 1;
    const int wn   = wid >> 1;
    const int er   = lane >> 2;
    const int ec   = (lane & 3) * 2;

    #pragma unroll
    for (int nt = 0; nt < 4; nt++) {
        const int col = n0 + wn * 32 + nt * 8 + ec;
        const float bx = bias[col], by = bias[col + 1];
        #pragma unroll
        for (int mt = 0; mt < 4; mt++) {
            const int row = m0 + wm * 64 + mt * 16 + er;
            *(float2*)&out[(size_t)row * DMODEL + col] =
                make_float2(d[mt][nt][0] + bx, d[mt][nt][1] + by);
            *(float2*)&out[(size_t)(row + 8) * DMODEL + col] =
                make_float2(d[mt][nt][2] + bx, d[mt][nt][3] + by);
        }
    }
}

// ---------------------------------------------------------------------------
// Flash attention on tensor cores (core verified R12; epilogue emits bf16 hi/lo)
// Block 256 thr = 8 warps; q-tile 128; k-tiles of 64. grid (16, 64)
// ---------------------------------------------------------------------------
__global__ __launch_bounds__(256) void attn_mma()
{
    __shared__ __align__(128) uint8_t sbuf[32768];

    const int t    = threadIdx.x;
    const int lane = t & 31;
    const int wq   = t >> 5;
    const int bh   = blockIdx.y;
    const int b    = bh >> 4, h = bh & 15;
    const int q0   = blockIdx.x * 128;

    const uint32_t sB   = smem_u32(sbuf);
    const uint32_t sKhi = sB, sKlo = sB + 8192, sVhi = sB + 16384, sVlo = sB + 24576;
    const uint32_t sQhi = sB, sQlo = sB + 16384;

    const size_t headbase = (size_t)bh * SEQ * HD;

    // ---- Phase A: stage Q, load persistent a-frags ----
    #pragma unroll
    for (int u = 0; u < 4; u++) {
        const int i   = t * 4 + u;
        const int row = i >> 3;
        const int ch  = i & 7;
        const uint32_t so = swz128(row, ch);
        const size_t g = (headbase + (size_t)(q0 + row) * HD + ch * 8) / 8;
        *(uint4*)(sbuf + (sQhi - sB) + so) = ((const uint4*)g_qhi)[g];
        *(uint4*)(sbuf + (sQlo - sB) + so) = ((const uint4*)g_qlo)[g];
    }
    __syncthreads();

    uint32_t qhi[4][4], qlo[4][4];
    {
        const int arow = wq * 16 + (lane & 15);
        const int acl  = lane >> 4;
        #pragma unroll
        for (int ks = 0; ks < 4; ks++) {
            const uint32_t off = swz128(arow, ks * 2 + acl);
            ldmatrix_x4(qhi[ks][0], qhi[ks][1], qhi[ks][2], qhi[ks][3], sQhi + off);
            ldmatrix_x4(qlo[ks][0], qlo[ks][1], qlo[ks][2], qlo[ks][3], sQlo + off);
        }
    }
    __syncthreads();

    const int er  = lane >> 2;
    const int ec  = (lane & 3) * 2;
    const int kbr = lane & 7;
    const int kbc = (lane >> 3) & 1;
    const int vbr = lane & 15;

    const int si0 = t * 2, si1 = t * 2 + 1;
    const uint32_t kso0 = swz128(si0 >> 3, si0 & 7);
    const uint32_t kso1 = swz128(si1 >> 3, si1 & 7);

    float m0 = -INFINITY, m1 = -INFINITY, l0 = 0.f, l1 = 0.f;
    float o[8][4];
    #pragma unroll
    for (int dt = 0; dt < 8; dt++)
        #pragma unroll
        for (int e = 0; e < 4; e++) o[dt][e] = 0.f;

    uint4 pf[8];
    {
        const size_t g0 = (headbase + (size_t)(si0 >> 3) * HD + (si0 & 7) * 8) / 8;
        const size_t g1 = (headbase + (size_t)(si1 >> 3) * HD + (si1 & 7) * 8) / 8;
        pf[0] = ((const uint4*)g_khi)[g0]; pf[1] = ((const uint4*)g_khi)[g1];
        pf[2] = ((const uint4*)g_klo)[g0]; pf[3] = ((const uint4*)g_klo)[g1];
        pf[4] = ((const uint4*)g_vhi)[g0]; pf[5] = ((const uint4*)g_vhi)[g1];
        pf[6] = ((const uint4*)g_vlo)[g0]; pf[7] = ((const uint4*)g_vlo)[g1];
    }

    for (int kt = 0; kt < SEQ / 64; kt++) {
        *(uint4*)(sbuf + 0     + kso0) = pf[0]; *(uint4*)(sbuf + 0     + kso1) = pf[1];
        *(uint4*)(sbuf + 8192  + kso0) = pf[2]; *(uint4*)(sbuf + 8192  + kso1) = pf[3];
        *(uint4*)(sbuf + 16384 + kso0) = pf[4]; *(uint4*)(sbuf + 16384 + kso1) = pf[5];
        *(uint4*)(sbuf + 24576 + kso0) = pf[6]; *(uint4*)(sbuf + 24576 + kso1) = pf[7];
        __syncthreads();

        if (kt + 1 < SEQ / 64) {
            const size_t kb = headbase + (size_t)(kt + 1) * 64 * HD;
            const size_t g0 = (kb + (size_t)(si0 >> 3) * HD + (si0 & 7) * 8) / 8;
            const size_t g1 = (kb + (size_t)(si1 >> 3) * HD + (si1 & 7) * 8) / 8;
            pf[0] = ((const uint4*)g_khi)[g0]; pf[1] = ((const uint4*)g_khi)[g1];
            pf[2] = ((const uint4*)g_klo)[g0]; pf[3] = ((const uint4*)g_klo)[g1];
            pf[4] = ((const uint4*)g_vhi)[g0]; pf[5] = ((const uint4*)g_vhi)[g1];
            pf[6] = ((const uint4*)g_vlo)[g0]; pf[7] = ((const uint4*)g_vlo)[g1];
        }

        float s[8][4];
        #pragma unroll
        for (int nt = 0; nt < 8; nt++)
            #pragma unroll
            for (int e = 0; e < 4; e++) s[nt][e] = 0.f;

        #pragma unroll
        for (int ks = 0; ks < 4; ks++) {
            #pragma unroll
            for (int nt = 0; nt < 8; nt++) {
                uint32_t bhh[2], bll[2];
                const uint32_t off = swz128(nt * 8 + kbr, ks * 2 + kbc);
                ldmatrix_x2(bhh[0], bhh[1], sKhi + off);
                ldmatrix_x2(bll[0], bll[1], sKlo + off);
                mma_bf16(s[nt], qhi[ks], bhh);
                mma_bf16(s[nt], qhi[ks], bll);
                mma_bf16(s[nt], qlo[ks], bhh);
            }
        }

        float mx0 = s[0][0], mx1 = s[0][2];
        #pragma unroll
        for (int nt = 0; nt < 8; nt++) {
            mx0 = fmaxf(mx0, fmaxf(s[nt][0], s[nt][1]));
            mx1 = fmaxf(mx1, fmaxf(s[nt][2], s[nt][3]));
        }
        mx0 = fmaxf(mx0, __shfl_xor_sync(0xffffffffu, mx0, 1));
        mx0 = fmaxf(mx0, __shfl_xor_sync(0xffffffffu, mx0, 2));
        mx1 = fmaxf(mx1, __shfl_xor_sync(0xffffffffu, mx1, 1));
        mx1 = fmaxf(mx1, __shfl_xor_sync(0xffffffffu, mx1, 2));

        const float mn0 = fmaxf(m0, mx0);
        const float mn1 = fmaxf(m1, mx1);
        const float al0 = __expf(m0 - mn0);
        const float al1 = __expf(m1 - mn1);
        m0 = mn0; m1 = mn1;

        float rs0 = 0.f, rs1 = 0.f;
        #pragma unroll
        for (int nt = 0; nt < 8; nt++) {
            s[nt][0] = __expf(s[nt][0] - mn0);
            s[nt][1] = __expf(s[nt][1] - mn0);
            s[nt][2] = __expf(s[nt][2] - mn1);
            s[nt][3] = __expf(s[nt][3] - mn1);
            rs0 += s[nt][0] + s[nt][1];
            rs1 += s[nt][2] + s[nt][3];
        }
        rs0 += __shfl_xor_sync(0xffffffffu, rs0, 1);
        rs0 += __shfl_xor_sync(0xffffffffu, rs0, 2);
        rs1 += __shfl_xor_sync(0xffffffffu, rs1, 1);
        rs1 += __shfl_xor_sync(0xffffffffu, rs1, 2);
        l0 = l0 * al0 + rs0;
        l1 = l1 * al1 + rs1;

        #pragma unroll
        for (int dt = 0; dt < 8; dt++) {
            o[dt][0] *= al0; o[dt][1] *= al0;
            o[dt][2] *= al1; o[dt][3] *= al1;
        }

        uint32_t pa_hi[4][4], pa_lo[4][4];
        #pragma unroll
        for (int kk = 0; kk < 4; kk++) {
            #pragma unroll
            for (int half = 0; half < 2; half++) {
                const float* sv = s[2*kk + half];
                float rh[4], rl[4];
                #pragma unroll
                for (int e = 0; e < 4; e++) {
                    __nv_bfloat16 hh = __float2bfloat16_rn(sv[e]);
                    rh[e] = __bfloat162float(hh);
                    rl[e] = sv[e] - rh[e];
                }
                pa_hi[kk][half*2 + 0] = pack_bf16(rh[0], rh[1]);
                pa_hi[kk][half*2 + 1] = pack_bf16(rh[2], rh[3]);
                pa_lo[kk][half*2 + 0] = pack_bf16(rl[0], rl[1]);
                pa_lo[kk][half*2 + 1] = pack_bf16(rl[2], rl[3]);
            }
        }

        #pragma unroll
        for (int kk = 0; kk < 4; kk++) {
            #pragma unroll
            for (int dt = 0; dt < 8; dt++) {
                uint32_t bvh[2], bvl[2];
                const uint32_t off = swz128(kk * 16 + vbr, dt);
                ldmatrix_x2t(bvh[0], bvh[1], sVhi + off);
                ldmatrix_x2t(bvl[0], bvl[1], sVlo + off);
                mma_bf16(o[dt], pa_hi[kk], bvh);
                mma_bf16(o[dt], pa_hi[kk], bvl);
                mma_bf16(o[dt], pa_lo[kk], bvh);
            }
        }
        __syncthreads();
    }

    // ---- epilogue: normalize, split to bf16 hi/lo -> g_ahi/g_alo [B*N, D] ----
    const float inv0 = 1.f / l0;
    const float inv1 = 1.f / l1;
    const int row0 = b * SEQ + q0 + wq * 16 + er;
    #pragma unroll
    for (int dt = 0; dt < 8; dt++) {
        const int col = h * HD + dt * 8 + ec;
        uint32_t uh, ul;
        split2(o[dt][0] * inv0, o[dt][1] * inv0, uh, ul);
        *(uint32_t*)&g_ahi[(size_t)row0 * DMODEL + col] = uh;
        *(uint32_t*)&g_alo[(size_t)row0 * DMODEL + col] = ul;
        split2(o[dt][2] * inv1, o[dt][3] * inv1, uh, ul);
        *(uint32_t*)&g_ahi[(size_t)(row0 + 8) * DMODEL + col] = uh;
        *(uint32_t*)&g_alo[(size_t)(row0 + 8) * DMODEL + col] = ul;
    }
}

// ---------------------------------------------------------------------------
extern "C" void kernel_launch(void* const* d_in, const int* in_sizes, int n_in,
                              void* d_out, int out_size)
{
    const float* x     = (const float*)d_in[0];   // [4,2048,1024]
    const float* w_qkv = (const float*)d_in[1];   // [3072,1024]
    const float* w_out = (const float*)d_in[2];   // [1024,1024]
    const float* b_out = (const float*)d_in[3];   // [1024]
    float* out = (float*)d_out;                   // [4,2048,1024]

    // 0) Pre-split inputs to bf16 hi/lo (globals bound in device code!)
    presplit_x <<<(ROWS * DMODEL) / (256 * 8), 256>>>(x);
    presplit_w1<<<(TD * DMODEL) / (256 * 8), 256>>>(w_qkv);
    presplit_w2<<<(DMODEL * DMODEL) / (256 * 8), 256>>>(w_out);

    // 1) QKV projection, fused per-head split-scatter (Q scaled)
    gemm1_tc<<<dim3(TD / 128, ROWS / 128), 256>>>();

    // 2) Flash attention on tensor cores -> g_ahi/g_alo
    attn_mma<<<dim3(SEQ / 128, NBH), 256>>>();

    // 3) Output projection + bias -> d_out
    gemm2_tc<<<dim3(DMODEL / 128, ROWS / 128), 256>>>(b_out, out);
}